// round 7
// baseline (speedup 1.0000x reference)
#include <cuda_runtime.h>
#include <cuda_bf16.h>
#include <math.h>
#include <stdint.h>

#define BATCH      4096
#define DIM        128
#define NFORM      256
#define NLIT       10752

// ---------------------------------------------------------------------------
// Helpers (portable PTX only: ldmatrix / mma.sync / cp.async)
// ---------------------------------------------------------------------------
__device__ __forceinline__ float ftanh(float v) {
    float r; asm("tanh.approx.f32 %0, %1;" : "=f"(r) : "f"(v)); return r;
}
__device__ __forceinline__ uint32_t smem_u32(const void* p) {
    uint32_t a;
    asm("{ .reg .u64 t; cvta.to.shared.u64 t, %1; cvt.u32.u64 %0, t; }" : "=r"(a) : "l"(p));
    return a;
}
__device__ __forceinline__ void ldsm_x4(uint32_t& r0, uint32_t& r1, uint32_t& r2, uint32_t& r3,
                                        uint32_t addr) {
    asm volatile("ldmatrix.sync.aligned.m8n8.x4.shared.b16 {%0,%1,%2,%3}, [%4];"
                 : "=r"(r0), "=r"(r1), "=r"(r2), "=r"(r3) : "r"(addr));
}
__device__ __forceinline__ void mma16816(float* c, uint32_t a0, uint32_t a1, uint32_t a2,
                                         uint32_t a3, uint32_t b0, uint32_t b1) {
    asm volatile("mma.sync.aligned.m16n8k16.row.col.f32.bf16.bf16.f32 "
                 "{%0,%1,%2,%3}, {%4,%5,%6,%7}, {%8,%9}, {%0,%1,%2,%3};"
                 : "+f"(c[0]), "+f"(c[1]), "+f"(c[2]), "+f"(c[3])
                 : "r"(a0), "r"(a1), "r"(a2), "r"(a3), "r"(b0), "r"(b1));
}
__device__ __forceinline__ void cpa16(uint32_t dst, const void* src, uint32_t srcsize) {
    asm volatile("cp.async.ca.shared.global [%0], [%1], 16, %2;"
                 :: "r"(dst), "l"(src), "r"(srcsize));
}
__device__ __forceinline__ void cpa_commit() { asm volatile("cp.async.commit_group;"); }
__device__ __forceinline__ void cpa_wait1()  { asm volatile("cp.async.wait_group 1;"); }
__device__ __forceinline__ void cpa_wait0()  { asm volatile("cp.async.wait_group 0;"); }

// ---------------------------------------------------------------------------
// Scratch (device globals)
// ---------------------------------------------------------------------------
__device__ float          g_dnnf[BATCH * NFORM];
__device__ float          g_c   [NFORM];
__device__ __nv_bfloat16  g_x_hi[BATCH * DIM];
__device__ __nv_bfloat16  g_x_lo[BATCH * DIM];
__device__ __nv_bfloat16  g_x2h [BATCH * DIM];
__device__ __nv_bfloat16  g_x2l [BATCH * DIM];
__device__ __nv_bfloat16  g_wt_hi[(size_t)NLIT * DIM];
__device__ __nv_bfloat16  g_wt_lo[(size_t)NLIT * DIM];
__device__ __nv_bfloat16  g_s2h [NFORM * DIM];   // sigma^2 split, [f][k]
__device__ __nv_bfloat16  g_s2l [NFORM * DIM];
__device__ __nv_bfloat16  g_m2h [NFORM * DIM];   // -2*mu*sigma^2 split
__device__ __nv_bfloat16  g_m2l [NFORM * DIM];

__device__ __forceinline__ void split1(float v, __nv_bfloat16& h, __nv_bfloat16& l) {
    h = __float2bfloat16(v);
    l = __float2bfloat16(v - __bfloat162float(h));
}
__device__ __forceinline__ void split2(float v0, float v1, uint32_t& hi, uint32_t& lo) {
    __nv_bfloat16 h0, l0, h1, l1;
    split1(v0, h0, l0); split1(v1, h1, l1);
    __nv_bfloat162 hh = __halves2bfloat162(h0, h1);
    __nv_bfloat162 ll = __halves2bfloat162(l0, l1);
    hi = *reinterpret_cast<uint32_t*>(&hh);
    lo = *reinterpret_cast<uint32_t*>(&ll);
}

// ---------------------------------------------------------------------------
// K0a: per-formula precompute: c[f], bf16 splits of sigma^2 and -2*mu*sigma^2
// ---------------------------------------------------------------------------
__global__ void k0_precompute(const float* __restrict__ mu,
                              const float* __restrict__ sigma) {
    int f = blockIdx.x, k = threadIdx.x;
    float sg = sigma[f * DIM + k];
    float m  = mu[f * DIM + k];
    float s2 = sg * sg;
    float m2 = -2.f * m * s2;
    __nv_bfloat16 h, l;
    split1(s2, h, l); g_s2h[f * DIM + k] = h; g_s2l[f * DIM + k] = l;
    split1(m2, h, l); g_m2h[f * DIM + k] = h; g_m2l[f * DIM + k] = l;
    float cp = m * m * s2;
    #pragma unroll
    for (int off = 16; off > 0; off >>= 1)
        cp += __shfl_xor_sync(0xFFFFFFFFu, cp, off);
    __shared__ float red[4];
    if ((k & 31) == 0) red[k >> 5] = cp;
    __syncthreads();
    if (k == 0) g_c[f] = red[0] + red[1] + red[2] + red[3];
}

// ---------------------------------------------------------------------------
// K0b: split x and x^2 into bf16 hi/lo
// ---------------------------------------------------------------------------
__global__ __launch_bounds__(256) void k0_split_x(const float* __restrict__ x) {
    int e = blockIdx.x * 256 + threadIdx.x;
    const float4* src = reinterpret_cast<const float4*>(x) + (size_t)e * 2;
    float4 a = src[0], b = src[1];
    float v[8] = {a.x, a.y, a.z, a.w, b.x, b.y, b.z, b.w};
    uint32_t hi[4], lo[4], qhi[4], qlo[4];
    #pragma unroll
    for (int p = 0; p < 4; ++p) {
        split2(v[2*p], v[2*p+1], hi[p], lo[p]);
        split2(v[2*p]*v[2*p], v[2*p+1]*v[2*p+1], qhi[p], qlo[p]);
    }
    reinterpret_cast<uint4*>(g_x_hi)[e] = make_uint4(hi[0], hi[1], hi[2], hi[3]);
    reinterpret_cast<uint4*>(g_x_lo)[e] = make_uint4(lo[0], lo[1], lo[2], lo[3]);
    reinterpret_cast<uint4*>(g_x2h)[e]  = make_uint4(qhi[0], qhi[1], qhi[2], qhi[3]);
    reinterpret_cast<uint4*>(g_x2l)[e]  = make_uint4(qlo[0], qlo[1], qlo[2], qlo[3]);
}

// ---------------------------------------------------------------------------
// K0c: masked W -> transposed (literal-major) bf16 hi/lo
// ---------------------------------------------------------------------------
__global__ __launch_bounds__(256) void k0_split_w(const float* __restrict__ w,
                                                  const float* __restrict__ lm) {
    __shared__ float s[128 * 65];
    const int l0  = blockIdx.x * 64;
    const int tid = threadIdx.x;
    for (int e = tid; e < 128 * 64; e += 256) {
        int k = e >> 6, j = e & 63;
        int l = l0 + j;
        int f;
        if      (l < 1536) f = l / 24;
        else if (l < 3840) f = 64  + (l - 1536) / 36;
        else if (l < 6912) f = 128 + (l - 3840) / 48;
        else               f = 192 + (l - 6912) / 60;
        float mk = (fabsf(lm[k * NFORM + f]) > 1.0f) ? 1.0f : 0.0f;
        s[k * 65 + j] = w[(size_t)k * NLIT + l] * mk;
    }
    __syncthreads();
    for (int e = tid; e < 64 * 16; e += 256) {
        int row = e >> 4, chunk = e & 15;
        uint32_t hi[4], lo[4];
        #pragma unroll
        for (int p = 0; p < 4; ++p)
            split2(s[(chunk * 8 + 2*p) * 65 + row], s[(chunk * 8 + 2*p + 1) * 65 + row],
                   hi[p], lo[p]);
        size_t l = l0 + row;
        reinterpret_cast<uint4*>(g_wt_hi + l * DIM)[chunk] = make_uint4(hi[0], hi[1], hi[2], hi[3]);
        reinterpret_cast<uint4*>(g_wt_lo + l * DIM)[chunk] = make_uint4(lo[0], lo[1], lo[2], lo[3]);
    }
}

// ---------------------------------------------------------------------------
// K1: HMMA literal GEMM, CTA M128 x N256, 8 warps of M64 x N64, virtual K=384
//     (hi*hi + lo*hi + hi*lo), 2-stage cp.async pipeline; 2-phase epilogue.
// ---------------------------------------------------------------------------
#define RS       144
#define SM_BIAS  0                           // 256 floats
#define SA0      1024
#define SA1      (SA0 + 128 * RS)            // 19456
#define SB0      (SA1 + 128 * RS)            // 37888
#define SB1      (SB0 + 256 * RS)            // 74752
#define K1_SMEM  (SB1 + 256 * RS)            // 111616

__device__ __forceinline__ void k1_prefetch(int kc, uint32_t sa, uint32_t sbb,
                                            int tid, int rowBase, int lb0, int BLIT) {
    const __nv_bfloat16* xsrc = (kc == 2 || kc == 3) ? g_x_lo : g_x_hi;
    const __nv_bfloat16* wsrc = (kc >= 4) ? g_wt_lo : g_wt_hi;
    const int koff = (kc & 1) * 64;
    #pragma unroll
    for (int i = 0; i < 4; ++i) {
        int e = tid + i * 256;
        int r = e >> 3, ch = e & 7;
        cpa16(sa + r * RS + ch * 16,
              xsrc + (size_t)(rowBase + r) * DIM + koff + ch * 8, 16);
    }
    #pragma unroll
    for (int i = 0; i < 8; ++i) {
        int e = tid + i * 256;
        int n = e >> 3, ch = e & 7;
        int s = n >> 6, j = n & 63;
        cpa16(sbb + n * RS + ch * 16,
              wsrc + (size_t)(lb0 + s * BLIT + j) * DIM + koff + ch * 8,
              (j < BLIT) ? 16u : 0u);
    }
}

__global__ __launch_bounds__(256) void k1_tensor(const float* __restrict__ bias) {
    extern __shared__ __align__(1024) char smem[];
    const uint32_t sb = smem_u32(smem);
    float* bs = reinterpret_cast<float*>(smem + SM_BIAS);

    const int tid     = threadIdx.x;
    const int wid     = tid >> 5;
    const int lane    = tid & 31;
    const int rowBase = blockIdx.x * 128;

    // ---- decode y-tile: 4 consecutive 64-blocks of one group ----
    const int yy = blockIdx.y;
    int BLIT, nd, nftb, f0g, lb0;
    if (yy < 8)       { BLIT = 48; nd = 2; nftb = 2; f0g = 8 * yy;             lb0 = 192 * yy; }
    else if (yy < 24) { int t = yy - 8;  BLIT = 36; nd = 3; nftb = 1; f0g = 64  + 4 * t; lb0 = 1536 + 144 * t; }
    else if (yy < 40) { int t = yy - 24; BLIT = 48; nd = 4; nftb = 1; f0g = 128 + 4 * t; lb0 = 3840 + 192 * t; }
    else              { int t = yy - 40; BLIT = 60; nd = 5; nftb = 1; f0g = 192 + 4 * t; lb0 = 6912 + 240 * t; }

    // ---- bias (256 cols) ----
    {
        int s = tid >> 6, j = tid & 63;
        bs[tid] = (j < BLIT) ? bias[lb0 + s * BLIT + j] : 0.f;
    }

    k1_prefetch(0, sb + SA0, sb + SB0, tid, rowBase, lb0, BLIT);
    cpa_commit();
    k1_prefetch(1, sb + SA1, sb + SB1, tid, rowBase, lb0, BLIT);
    cpa_commit();

    // warp grid: 2(M) x 4(N), warp tile M64 x N64
    const int wm = wid & 1, wn = wid >> 1;
    const int mrow = wm * 64, ncol = wn * 64;
    const uint32_t apat = (uint32_t)((mrow + (lane & 15)) * RS + (lane >> 4) * 16);
    const uint32_t bpat = (uint32_t)((ncol + (lane & 7) + ((lane >> 4) & 1) * 8) * RS +
                                     ((lane >> 3) & 1) * 16);

    float acc[8][4][4];
    #pragma unroll
    for (int nt = 0; nt < 8; ++nt)
        #pragma unroll
        for (int mt = 0; mt < 4; ++mt)
            #pragma unroll
            for (int j = 0; j < 4; ++j) acc[nt][mt][j] = 0.f;

    #pragma unroll
    for (int kc = 0; kc < 6; ++kc) {
        if (kc < 5) cpa_wait1(); else cpa_wait0();
        __syncthreads();
        const uint32_t sa  = sb + ((kc & 1) ? SA1 : SA0);
        const uint32_t sbb = sb + ((kc & 1) ? SB1 : SB0);
        #pragma unroll
        for (int kk = 0; kk < 4; ++kk) {
            uint32_t a[4][4];
            #pragma unroll
            for (int mt = 0; mt < 4; ++mt)
                ldsm_x4(a[mt][0], a[mt][1], a[mt][2], a[mt][3],
                        sa + apat + mt * (16 * RS) + kk * 32);
            #pragma unroll
            for (int nt2 = 0; nt2 < 4; ++nt2) {
                uint32_t b0, b1, b2, b3;
                ldsm_x4(b0, b1, b2, b3, sbb + bpat + nt2 * (16 * RS) + kk * 32);
                #pragma unroll
                for (int mt = 0; mt < 4; ++mt) {
                    mma16816(acc[2*nt2    ][mt], a[mt][0], a[mt][1], a[mt][2], a[mt][3], b0, b1);
                    mma16816(acc[2*nt2 + 1][mt], a[mt][0], a[mt][1], a[mt][2], a[mt][3], b2, b3);
                }
            }
        }
        if (kc < 4) {
            __syncthreads();
            k1_prefetch(kc + 2, sa, sbb, tid, rowBase, lb0, BLIT);
            cpa_commit();
        }
    }
    __syncthreads();

    // ---- 2-phase epilogue: phase h handles global cols [h*128, h*128+128) ----
    float* ct = reinterpret_cast<float*>(smem + SA0);    // [128][130]
    const int gidr = lane >> 2, tig = lane & 3;
    const int nf_ph = 2 * nftb;

    #pragma unroll
    for (int h = 0; h < 2; ++h) {
        if ((wn >> 1) == h) {
            const int cbase = (wn & 1) * 64;              // local col base
            #pragma unroll
            for (int nt = 0; nt < 8; ++nt) {
                const int c0l = cbase + nt * 8 + 2 * tig;
                const int c0g = h * 128 + c0l;
                #pragma unroll
                for (int mt = 0; mt < 4; ++mt) {
                    const int r0 = mrow + mt * 16 + gidr;
                    ct[r0 * 130 + c0l]           = ftanh(acc[nt][mt][0] + bs[c0g]);
                    ct[r0 * 130 + c0l + 1]       = ftanh(acc[nt][mt][1] + bs[c0g + 1]);
                    ct[(r0 + 8) * 130 + c0l]     = ftanh(acc[nt][mt][2] + bs[c0g]);
                    ct[(r0 + 8) * 130 + c0l + 1] = ftanh(acc[nt][mt][3] + bs[c0g + 1]);
                }
            }
        }
        __syncthreads();
        for (int task = tid; task < 128 * nf_ph; task += 256) {
            const int row = task & 127;
            const int fi  = task >> 7;
            const int cb  = (nftb == 2) ? ((fi >> 1) * 64 + (fi & 1) * 24) : (fi * 64);
            const float* cr = &ct[row * 130 + cb];
            float fs = 0.f;
            int off = 0;
            #pragma unroll
            for (int dd = 0; dd < 3; ++dd) {
                const int d = 2 + 2 * dd;
                for (int c = 0; c < nd; ++c) {
                    float sA = 0.f;
                    #pragma unroll
                    for (int u = 0; u < 6; ++u)
                        if (u < d) sA += cr[off + u];
                    fs += ftanh(sA - (float)d + 1.5f);
                    off += d;
                }
            }
            g_dnnf[(size_t)(rowBase + row) * NFORM + f0g + h * nf_ph + fi] =
                ftanh(fs + 3.0f * (float)nd - 1.5f);
        }
        __syncthreads();
    }
}

// ---------------------------------------------------------------------------
// K2 (fused with softmax): v = sum sig^2 x^2 - 2 sum mu sig^2 x + c  via HMMA
//   virtual K = 768 (2 GEMMs x 3 split passes); CTA M64 x N256 (all formulas),
//   8 warps of M32 x N64; epilogue: loc, row softmax, multiply g_dnnf -> out.
// ---------------------------------------------------------------------------
#define K2A0   0
#define K2A1   (K2A0 + 64 * RS)              // 9216
#define K2B0   (K2A1 + 64 * RS)              // 18432
#define K2B1   (K2B0 + 256 * RS)             // 55296
#define K2SCR  (K2B1 + 256 * RS)             // 92160  (64 rows x 4 warps floats)
#define K2_SMEM (K2SCR + 64 * 4 * 4)         // 93184

__device__ __forceinline__ void k2_prefetch(int kc, uint32_t sa, uint32_t sbb,
                                            int tid, int rowBase) {
    const int p = kc >> 1, koff = (kc & 1) * 64;
    const __nv_bfloat16* asrc =
        (p == 0 || p == 2) ? g_x2h : (p == 1) ? g_x2l :
        (p == 3 || p == 5) ? g_x_hi : g_x_lo;
    const __nv_bfloat16* bsrc =
        (p <= 1) ? g_s2h : (p == 2) ? g_s2l : (p <= 4) ? g_m2h : g_m2l;
    #pragma unroll
    for (int i = 0; i < 2; ++i) {
        int e = tid + i * 256;
        int r = e >> 3, ch = e & 7;
        cpa16(sa + r * RS + ch * 16,
              asrc + (size_t)(rowBase + r) * DIM + koff + ch * 8, 16);
    }
    #pragma unroll
    for (int i = 0; i < 8; ++i) {
        int e = tid + i * 256;
        int n = e >> 3, ch = e & 7;
        cpa16(sbb + n * RS + ch * 16, bsrc + (size_t)n * DIM + koff + ch * 8, 16);
    }
}

__global__ __launch_bounds__(256) void k2_fused(const float* __restrict__ temp,
                                                float* __restrict__ out) {
    extern __shared__ __align__(1024) char smem[];
    const uint32_t sb = smem_u32(smem);
    float* scr = reinterpret_cast<float*>(smem + K2SCR);  // [64][4]

    const int tid     = threadIdx.x;
    const int wid     = tid >> 5;
    const int lane    = tid & 31;
    const int rowBase = blockIdx.x * 64;

    k2_prefetch(0, sb + K2A0, sb + K2B0, tid, rowBase);
    cpa_commit();
    k2_prefetch(1, sb + K2A1, sb + K2B1, tid, rowBase);
    cpa_commit();

    // warp grid: 2(M) x 4(N), warp tile M32 x N64
    const int wm = wid & 1, wn = wid >> 1;
    const int mrow = wm * 32, ncol = wn * 64;
    const uint32_t apat = (uint32_t)((mrow + (lane & 15)) * RS + (lane >> 4) * 16);
    const uint32_t bpat = (uint32_t)((ncol + (lane & 7) + ((lane >> 4) & 1) * 8) * RS +
                                     ((lane >> 3) & 1) * 16);

    float acc[8][2][4];
    #pragma unroll
    for (int nt = 0; nt < 8; ++nt)
        #pragma unroll
        for (int mt = 0; mt < 2; ++mt)
            #pragma unroll
            for (int j = 0; j < 4; ++j) acc[nt][mt][j] = 0.f;

    #pragma unroll
    for (int kc = 0; kc < 12; ++kc) {
        if (kc < 11) cpa_wait1(); else cpa_wait0();
        __syncthreads();
        const uint32_t sa  = sb + ((kc & 1) ? K2A1 : K2A0);
        const uint32_t sbb = sb + ((kc & 1) ? K2B1 : K2B0);
        #pragma unroll
        for (int kk = 0; kk < 4; ++kk) {
            uint32_t a[2][4];
            #pragma unroll
            for (int mt = 0; mt < 2; ++mt)
                ldsm_x4(a[mt][0], a[mt][1], a[mt][2], a[mt][3],
                        sa + apat + mt * (16 * RS) + kk * 32);
            #pragma unroll
            for (int nt2 = 0; nt2 < 4; ++nt2) {
                uint32_t b0, b1, b2, b3;
                ldsm_x4(b0, b1, b2, b3, sbb + bpat + nt2 * (16 * RS) + kk * 32);
                #pragma unroll
                for (int mt = 0; mt < 2; ++mt) {
                    mma16816(acc[2*nt2    ][mt], a[mt][0], a[mt][1], a[mt][2], a[mt][3], b0, b1);
                    mma16816(acc[2*nt2 + 1][mt], a[mt][0], a[mt][1], a[mt][2], a[mt][3], b2, b3);
                }
            }
        }
        if (kc < 10) {
            __syncthreads();
            k2_prefetch(kc + 2, sa, sbb, tid, rowBase);
            cpa_commit();
        }
    }
    __syncthreads();

    // ---- epilogue: z = sigmoid(T) * exp(-sqrt(v)) ----
    const float s = 1.f / (1.f + __expf(-temp[0]));
    const int gidr = lane >> 2, tig = lane & 3;

    #pragma unroll
    for (int nt = 0; nt < 8; ++nt) {
        #pragma unroll
        for (int mt = 0; mt < 2; ++mt) {
            #pragma unroll
            for (int j = 0; j < 4; ++j) {
                const int col = ncol + nt * 8 + 2 * tig + (j & 1);
                float v = acc[nt][mt][j] + __ldg(&g_c[col]);
                acc[nt][mt][j] = s * __expf(-__fsqrt_rn(fmaxf(v, 0.f)));
            }
        }
    }

    // ---- row max across 256 cols (shfl over tig, smem across 4 N-warps) ----
    float rmax[2][2];
    #pragma unroll
    for (int mt = 0; mt < 2; ++mt)
        #pragma unroll
        for (int hf = 0; hf < 2; ++hf) {
            float m = -1e30f;
            #pragma unroll
            for (int nt = 0; nt < 8; ++nt) {
                m = fmaxf(m, acc[nt][mt][2*hf]);
                m = fmaxf(m, acc[nt][mt][2*hf + 1]);
            }
            m = fmaxf(m, __shfl_xor_sync(0xFFFFFFFFu, m, 1));
            m = fmaxf(m, __shfl_xor_sync(0xFFFFFFFFu, m, 2));
            rmax[mt][hf] = m;
            if (tig == 0) scr[(mrow + mt * 16 + gidr + hf * 8) * 4 + wn] = m;
        }
    __syncthreads();
    #pragma unroll
    for (int mt = 0; mt < 2; ++mt)
        #pragma unroll
        for (int hf = 0; hf < 2; ++hf) {
            const float* p = &scr[(mrow + mt * 16 + gidr + hf * 8) * 4];
            rmax[mt][hf] = fmaxf(fmaxf(p[0], p[1]), fmaxf(p[2], p[3]));
        }
    __syncthreads();

    // ---- e = exp(z - m); row sums ----
    float rsum[2][2];
    #pragma unroll
    for (int mt = 0; mt < 2; ++mt)
        #pragma unroll
        for (int hf = 0; hf < 2; ++hf) {
            float sm = 0.f;
            #pragma unroll
            for (int nt = 0; nt < 8; ++nt) {
                acc[nt][mt][2*hf]     = __expf(acc[nt][mt][2*hf]     - rmax[mt][hf]);
                acc[nt][mt][2*hf + 1] = __expf(acc[nt][mt][2*hf + 1] - rmax[mt][hf]);
                sm += acc[nt][mt][2*hf] + acc[nt][mt][2*hf + 1];
            }
            sm += __shfl_xor_sync(0xFFFFFFFFu, sm, 1);
            sm += __shfl_xor_sync(0xFFFFFFFFu, sm, 2);
            if (tig == 0) scr[(mrow + mt * 16 + gidr + hf * 8) * 4 + wn] = sm;
        }
    __syncthreads();
    #pragma unroll
    for (int mt = 0; mt < 2; ++mt)
        #pragma unroll
        for (int hf = 0; hf < 2; ++hf) {
            const float* p = &scr[(mrow + mt * 16 + gidr + hf * 8) * 4];
            rsum[mt][hf] = 1.f / (p[0] + p[1] + p[2] + p[3]);
        }

    // ---- out = dnnf * softmax ----
    #pragma unroll
    for (int mt = 0; mt < 2; ++mt)
        #pragma unroll
        for (int hf = 0; hf < 2; ++hf) {
            const size_t grow = (size_t)(rowBase + mrow + mt * 16 + gidr + hf * 8);
            const float inv = rsum[mt][hf];
            #pragma unroll
            for (int nt = 0; nt < 8; ++nt) {
                const int col = ncol + nt * 8 + 2 * tig;
                const size_t idx = grow * NFORM + col;
                out[idx]     = g_dnnf[idx]     * acc[nt][mt][2*hf]     * inv;
                out[idx + 1] = g_dnnf[idx + 1] * acc[nt][mt][2*hf + 1] * inv;
            }
        }
}

// ---------------------------------------------------------------------------
extern "C" void kernel_launch(void* const* d_in, const int* in_sizes, int n_in,
                              void* d_out, int out_size) {
    const float* x     = (const float*)d_in[0];
    const float* w     = (const float*)d_in[1];
    const float* bias  = (const float*)d_in[2];
    const float* lm    = (const float*)d_in[3];
    const float* mu    = (const float*)d_in[4];
    const float* sigma = (const float*)d_in[5];
    const float* temp  = (const float*)d_in[6];
    float* out = (float*)d_out;

    cudaFuncSetAttribute(k1_tensor, cudaFuncAttributeMaxDynamicSharedMemorySize, K1_SMEM);
    cudaFuncSetAttribute(k2_fused,  cudaFuncAttributeMaxDynamicSharedMemorySize, K2_SMEM);

    k0_precompute<<<NFORM, DIM>>>(mu, sigma);
    k0_split_x<<<BATCH * DIM / (256 * 8), 256>>>(x);
    k0_split_w<<<NLIT / 64, 256>>>(w, lm);
    k1_tensor<<<dim3(32, 56), 256, K1_SMEM>>>(bias);
    k2_fused<<<BATCH / 64, 256, K2_SMEM>>>(temp, out);
}

// round 9
// speedup vs baseline: 1.1473x; 1.1473x over previous
#include <cuda_runtime.h>
#include <cuda_bf16.h>
#include <math.h>
#include <stdint.h>

#define BATCH      4096
#define DIM        128
#define NFORM      256
#define NLIT       10752

// ---------------------------------------------------------------------------
// Helpers (portable PTX only: ldmatrix / mma.sync / cp.async)
// ---------------------------------------------------------------------------
__device__ __forceinline__ float ftanh(float v) {
    float r; asm("tanh.approx.f32 %0, %1;" : "=f"(r) : "f"(v)); return r;
}
__device__ __forceinline__ uint32_t smem_u32(const void* p) {
    uint32_t a;
    asm("{ .reg .u64 t; cvta.to.shared.u64 t, %1; cvt.u32.u64 %0, t; }" : "=r"(a) : "l"(p));
    return a;
}
__device__ __forceinline__ void ldsm_x4(uint32_t& r0, uint32_t& r1, uint32_t& r2, uint32_t& r3,
                                        uint32_t addr) {
    asm volatile("ldmatrix.sync.aligned.m8n8.x4.shared.b16 {%0,%1,%2,%3}, [%4];"
                 : "=r"(r0), "=r"(r1), "=r"(r2), "=r"(r3) : "r"(addr));
}
__device__ __forceinline__ void mma16816(float* c, uint32_t a0, uint32_t a1, uint32_t a2,
                                         uint32_t a3, uint32_t b0, uint32_t b1) {
    asm volatile("mma.sync.aligned.m16n8k16.row.col.f32.bf16.bf16.f32 "
                 "{%0,%1,%2,%3}, {%4,%5,%6,%7}, {%8,%9}, {%0,%1,%2,%3};"
                 : "+f"(c[0]), "+f"(c[1]), "+f"(c[2]), "+f"(c[3])
                 : "r"(a0), "r"(a1), "r"(a2), "r"(a3), "r"(b0), "r"(b1));
}
__device__ __forceinline__ void cpa16(uint32_t dst, const void* src, uint32_t srcsize) {
    asm volatile("cp.async.ca.shared.global [%0], [%1], 16, %2;"
                 :: "r"(dst), "l"(src), "r"(srcsize));
}
__device__ __forceinline__ void cpa_commit() { asm volatile("cp.async.commit_group;"); }
__device__ __forceinline__ void cpa_wait1()  { asm volatile("cp.async.wait_group 1;"); }
__device__ __forceinline__ void cpa_wait0()  { asm volatile("cp.async.wait_group 0;"); }

// ---------------------------------------------------------------------------
// Scratch (device globals)
// ---------------------------------------------------------------------------
__device__ float          g_dnnf[BATCH * NFORM];
__device__ float          g_c   [NFORM];
__device__ __nv_bfloat16  g_x_hi[BATCH * DIM];
__device__ __nv_bfloat16  g_x_lo[BATCH * DIM];
__device__ __nv_bfloat16  g_x2h [BATCH * DIM];
__device__ __nv_bfloat16  g_x2l [BATCH * DIM];
__device__ __nv_bfloat16  g_wt_hi[(size_t)NLIT * DIM];
__device__ __nv_bfloat16  g_wt_lo[(size_t)NLIT * DIM];
__device__ __nv_bfloat16  g_s2h [NFORM * DIM];
__device__ __nv_bfloat16  g_s2l [NFORM * DIM];
__device__ __nv_bfloat16  g_m2h [NFORM * DIM];
__device__ __nv_bfloat16  g_m2l [NFORM * DIM];

__device__ __forceinline__ void split1(float v, __nv_bfloat16& h, __nv_bfloat16& l) {
    h = __float2bfloat16(v);
    l = __float2bfloat16(v - __bfloat162float(h));
}
__device__ __forceinline__ void split2(float v0, float v1, uint32_t& hi, uint32_t& lo) {
    __nv_bfloat16 h0, l0, h1, l1;
    split1(v0, h0, l0); split1(v1, h1, l1);
    __nv_bfloat162 hh = __halves2bfloat162(h0, h1);
    __nv_bfloat162 ll = __halves2bfloat162(l0, l1);
    hi = *reinterpret_cast<uint32_t*>(&hh);
    lo = *reinterpret_cast<uint32_t*>(&ll);
}

// ---------------------------------------------------------------------------
// K0a: c[f] + bf16 splits of sigma^2 and -2*mu*sigma^2
// ---------------------------------------------------------------------------
__global__ void k0_precompute(const float* __restrict__ mu,
                              const float* __restrict__ sigma) {
    int f = blockIdx.x, k = threadIdx.x;
    float sg = sigma[f * DIM + k];
    float m  = mu[f * DIM + k];
    float s2 = sg * sg;
    float m2 = -2.f * m * s2;
    __nv_bfloat16 h, l;
    split1(s2, h, l); g_s2h[f * DIM + k] = h; g_s2l[f * DIM + k] = l;
    split1(m2, h, l); g_m2h[f * DIM + k] = h; g_m2l[f * DIM + k] = l;
    float cp = m * m * s2;
    #pragma unroll
    for (int off = 16; off > 0; off >>= 1)
        cp += __shfl_xor_sync(0xFFFFFFFFu, cp, off);
    __shared__ float red[4];
    if ((k & 31) == 0) red[k >> 5] = cp;
    __syncthreads();
    if (k == 0) g_c[f] = red[0] + red[1] + red[2] + red[3];
}

// ---------------------------------------------------------------------------
// K0b: split x and x^2 into bf16 hi/lo
// ---------------------------------------------------------------------------
__global__ __launch_bounds__(256) void k0_split_x(const float* __restrict__ x) {
    int e = blockIdx.x * 256 + threadIdx.x;
    const float4* src = reinterpret_cast<const float4*>(x) + (size_t)e * 2;
    float4 a = src[0], b = src[1];
    float v[8] = {a.x, a.y, a.z, a.w, b.x, b.y, b.z, b.w};
    uint32_t hi[4], lo[4], qhi[4], qlo[4];
    #pragma unroll
    for (int p = 0; p < 4; ++p) {
        split2(v[2*p], v[2*p+1], hi[p], lo[p]);
        split2(v[2*p]*v[2*p], v[2*p+1]*v[2*p+1], qhi[p], qlo[p]);
    }
    reinterpret_cast<uint4*>(g_x_hi)[e] = make_uint4(hi[0], hi[1], hi[2], hi[3]);
    reinterpret_cast<uint4*>(g_x_lo)[e] = make_uint4(lo[0], lo[1], lo[2], lo[3]);
    reinterpret_cast<uint4*>(g_x2h)[e]  = make_uint4(qhi[0], qhi[1], qhi[2], qhi[3]);
    reinterpret_cast<uint4*>(g_x2l)[e]  = make_uint4(qlo[0], qlo[1], qlo[2], qlo[3]);
}

// ---------------------------------------------------------------------------
// K0c: masked W -> transposed (literal-major) bf16 hi/lo
// ---------------------------------------------------------------------------
__global__ __launch_bounds__(256) void k0_split_w(const float* __restrict__ w,
                                                  const float* __restrict__ lm) {
    __shared__ float s[128 * 65];
    const int l0  = blockIdx.x * 64;
    const int tid = threadIdx.x;
    for (int e = tid; e < 128 * 64; e += 256) {
        int k = e >> 6, j = e & 63;
        int l = l0 + j;
        int f;
        if      (l < 1536) f = l / 24;
        else if (l < 3840) f = 64  + (l - 1536) / 36;
        else if (l < 6912) f = 128 + (l - 3840) / 48;
        else               f = 192 + (l - 6912) / 60;
        float mk = (fabsf(lm[k * NFORM + f]) > 1.0f) ? 1.0f : 0.0f;
        s[k * 65 + j] = w[(size_t)k * NLIT + l] * mk;
    }
    __syncthreads();
    for (int e = tid; e < 64 * 16; e += 256) {
        int row = e >> 4, chunk = e & 15;
        uint32_t hi[4], lo[4];
        #pragma unroll
        for (int p = 0; p < 4; ++p)
            split2(s[(chunk * 8 + 2*p) * 65 + row], s[(chunk * 8 + 2*p + 1) * 65 + row],
                   hi[p], lo[p]);
        size_t l = l0 + row;
        reinterpret_cast<uint4*>(g_wt_hi + l * DIM)[chunk] = make_uint4(hi[0], hi[1], hi[2], hi[3]);
        reinterpret_cast<uint4*>(g_wt_lo + l * DIM)[chunk] = make_uint4(lo[0], lo[1], lo[2], lo[3]);
    }
}

// ---------------------------------------------------------------------------
// K1: HMMA literal GEMM, CTA M128 x N128 (densely packed formulas), 8 warps
//     of M32 x N64, virtual K=384 (hi*hi + lo*hi + hi*lo), 2-stage cp.async.
// ---------------------------------------------------------------------------
#define RS       144
#define SM_BIAS  0                           // 128 floats
#define SA0      1024
#define SA1      (SA0 + 128 * RS)            // 19456
#define SB0      (SA1 + 128 * RS)            // 37888
#define SB1      (SB0 + 128 * RS)            // 56320
#define K1_SMEM  (SB1 + 128 * RS)            // 74752

__device__ __forceinline__ void k1_prefetch(int kc, uint32_t sa, uint32_t sbb,
                                            int tid, int rowBase, int lb0, int LIVE) {
    const __nv_bfloat16* xsrc = (kc == 2 || kc == 3) ? g_x_lo : g_x_hi;
    const __nv_bfloat16* wsrc = (kc >= 4) ? g_wt_lo : g_wt_hi;
    const int koff = (kc & 1) * 64;
    #pragma unroll
    for (int i = 0; i < 4; ++i) {
        int e = tid + i * 256;
        int r = e >> 3, ch = e & 7;
        cpa16(sa + r * RS + ch * 16,
              xsrc + (size_t)(rowBase + r) * DIM + koff + ch * 8, 16);
    }
    #pragma unroll
    for (int i = 0; i < 4; ++i) {
        int e = tid + i * 256;
        int n = e >> 3, ch = e & 7;
        cpa16(sbb + n * RS + ch * 16,
              wsrc + (size_t)(lb0 + n) * DIM + koff + ch * 8,
              (n < LIVE) ? 16u : 0u);
    }
}

__global__ __launch_bounds__(256, 2) void k1_tensor(const float* __restrict__ bias) {
    extern __shared__ __align__(1024) char smem[];
    const uint32_t sb = smem_u32(smem);
    float* bs = reinterpret_cast<float*>(smem + SM_BIAS);

    const int tid     = threadIdx.x;
    const int wid     = tid >> 5;
    const int lane    = tid & 31;
    const int rowBase = blockIdx.x * 128;

    // ---- dense-packed tile decode ----
    // G0: 13 tiles x up to 5 formulas(24) ; G1: 22 x up to 3(36) ;
    // G2: 32 x 2(48) ; G3: 32 x 2(60)
    const int yy = blockIdx.y;
    int LF, nd, nf, f0g, lb0;
    if (yy < 13)      { LF = 24; nd = 2; nf = (yy == 12) ? 4 : 5; f0g = 5 * yy;          lb0 = 120 * yy; }
    else if (yy < 35) { int t = yy - 13; LF = 36; nd = 3; nf = (t == 21) ? 1 : 3; f0g = 64  + 3 * t; lb0 = 1536 + 108 * t; }
    else if (yy < 67) { int t = yy - 35; LF = 48; nd = 4; nf = 2; f0g = 128 + 2 * t; lb0 = 3840 + 96 * t; }
    else              { int t = yy - 67; LF = 60; nd = 5; nf = 2; f0g = 192 + 2 * t; lb0 = 6912 + 120 * t; }
    const int LIVE = nf * LF;

    if (tid < 128) bs[tid] = (tid < LIVE) ? bias[lb0 + tid] : 0.f;

    k1_prefetch(0, sb + SA0, sb + SB0, tid, rowBase, lb0, LIVE);
    cpa_commit();
    k1_prefetch(1, sb + SA1, sb + SB1, tid, rowBase, lb0, LIVE);
    cpa_commit();

    // warp grid 4(M) x 2(N): warp tile M32 x N64
    const int mrow = (wid & 3) * 32;
    const int ncol = (wid >> 2) * 64;
    const uint32_t apat = (uint32_t)((mrow + (lane & 15)) * RS + (lane >> 4) * 16);
    const uint32_t bpat = (uint32_t)((ncol + (lane & 7) + ((lane >> 4) & 1) * 8) * RS +
                                     ((lane >> 3) & 1) * 16);

    float acc[8][2][4];
    #pragma unroll
    for (int nt = 0; nt < 8; ++nt)
        #pragma unroll
        for (int mt = 0; mt < 2; ++mt)
            #pragma unroll
            for (int j = 0; j < 4; ++j) acc[nt][mt][j] = 0.f;

    #pragma unroll
    for (int kc = 0; kc < 6; ++kc) {
        if (kc < 5) cpa_wait1(); else cpa_wait0();
        __syncthreads();
        const uint32_t sa  = sb + ((kc & 1) ? SA1 : SA0);
        const uint32_t sbb = sb + ((kc & 1) ? SB1 : SB0);
        #pragma unroll
        for (int kk = 0; kk < 4; ++kk) {
            uint32_t a[2][4];
            #pragma unroll
            for (int mt = 0; mt < 2; ++mt)
                ldsm_x4(a[mt][0], a[mt][1], a[mt][2], a[mt][3],
                        sa + apat + mt * (16 * RS) + kk * 32);
            #pragma unroll
            for (int nt2 = 0; nt2 < 4; ++nt2) {
                uint32_t b0, b1, b2, b3;
                ldsm_x4(b0, b1, b2, b3, sbb + bpat + nt2 * (16 * RS) + kk * 32);
                #pragma unroll
                for (int mt = 0; mt < 2; ++mt) {
                    mma16816(acc[2*nt2    ][mt], a[mt][0], a[mt][1], a[mt][2], a[mt][3], b0, b1);
                    mma16816(acc[2*nt2 + 1][mt], a[mt][0], a[mt][1], a[mt][2], a[mt][3], b2, b3);
                }
            }
        }
        if (kc < 4) {
            __syncthreads();
            k1_prefetch(kc + 2, sa, sbb, tid, rowBase, lb0, LIVE);
            cpa_commit();
        }
    }
    __syncthreads();

    // ---- tanh(literal) -> ct[128][130] (reuses stage smem) ----
    float* ct = reinterpret_cast<float*>(smem + SA0);
    {
        const int gidr = lane >> 2, tig = lane & 3;
        #pragma unroll
        for (int nt = 0; nt < 8; ++nt) {
            const int c0 = ncol + nt * 8 + 2 * tig;
            #pragma unroll
            for (int mt = 0; mt < 2; ++mt) {
                const int r0 = mrow + mt * 16 + gidr;
                ct[r0 * 130 + c0]           = ftanh(acc[nt][mt][0] + bs[c0]);
                ct[r0 * 130 + c0 + 1]       = ftanh(acc[nt][mt][1] + bs[c0 + 1]);
                ct[(r0 + 8) * 130 + c0]     = ftanh(acc[nt][mt][2] + bs[c0]);
                ct[(r0 + 8) * 130 + c0 + 1] = ftanh(acc[nt][mt][3] + bs[c0 + 1]);
            }
        }
    }
    __syncthreads();

    // ---- segmented reduce: nd conjs each of depth 2/4/6 -> formula ----
    for (int task = tid; task < 128 * nf; task += 256) {
        const int row = task & 127;
        const int fi  = task >> 7;
        const float* cr = &ct[row * 130 + fi * LF];
        float fs = 0.f;
        int off = 0;
        #pragma unroll
        for (int dd = 0; dd < 3; ++dd) {
            const int d = 2 + 2 * dd;
            for (int c = 0; c < nd; ++c) {
                float sA = 0.f;
                #pragma unroll
                for (int u = 0; u < 6; ++u)
                    if (u < d) sA += cr[off + u];
                fs += ftanh(sA - (float)d + 1.5f);
                off += d;
            }
        }
        g_dnnf[(size_t)(rowBase + row) * NFORM + f0g + fi] =
            ftanh(fs + 3.0f * (float)nd - 1.5f);
    }
}

// ---------------------------------------------------------------------------
// K2 fused: v GEMM (virtual K=768) + loc + row softmax + multiply -> out
// ---------------------------------------------------------------------------
#define K2A0   0
#define K2A1   (K2A0 + 64 * RS)
#define K2B0   (K2A1 + 64 * RS)
#define K2B1   (K2B0 + 256 * RS)
#define K2SCR  (K2B1 + 256 * RS)
#define K2_SMEM (K2SCR + 64 * 4 * 4)

__device__ __forceinline__ void k2_prefetch(int kc, uint32_t sa, uint32_t sbb,
                                            int tid, int rowBase) {
    const int p = kc >> 1, koff = (kc & 1) * 64;
    const __nv_bfloat16* asrc =
        (p == 0 || p == 2) ? g_x2h : (p == 1) ? g_x2l :
        (p == 3 || p == 5) ? g_x_hi : g_x_lo;
    const __nv_bfloat16* bsrc =
        (p <= 1) ? g_s2h : (p == 2) ? g_s2l : (p <= 4) ? g_m2h : g_m2l;
    #pragma unroll
    for (int i = 0; i < 2; ++i) {
        int e = tid + i * 256;
        int r = e >> 3, ch = e & 7;
        cpa16(sa + r * RS + ch * 16,
              asrc + (size_t)(rowBase + r) * DIM + koff + ch * 8, 16);
    }
    #pragma unroll
    for (int i = 0; i < 8; ++i) {
        int e = tid + i * 256;
        int n = e >> 3, ch = e & 7;
        cpa16(sbb + n * RS + ch * 16, bsrc + (size_t)n * DIM + koff + ch * 8, 16);
    }
}

__global__ __launch_bounds__(256) void k2_fused(const float* __restrict__ temp,
                                                float* __restrict__ out) {
    extern __shared__ __align__(1024) char smem[];
    const uint32_t sb = smem_u32(smem);
    float* scr = reinterpret_cast<float*>(smem + K2SCR);

    const int tid     = threadIdx.x;
    const int wid     = tid >> 5;
    const int lane    = tid & 31;
    const int rowBase = blockIdx.x * 64;

    k2_prefetch(0, sb + K2A0, sb + K2B0, tid, rowBase);
    cpa_commit();
    k2_prefetch(1, sb + K2A1, sb + K2B1, tid, rowBase);
    cpa_commit();

    const int wm = wid & 1, wn = wid >> 1;
    const int mrow = wm * 32, ncol = wn * 64;
    const uint32_t apat = (uint32_t)((mrow + (lane & 15)) * RS + (lane >> 4) * 16);
    const uint32_t bpat = (uint32_t)((ncol + (lane & 7) + ((lane >> 4) & 1) * 8) * RS +
                                     ((lane >> 3) & 1) * 16);

    float acc[8][2][4];
    #pragma unroll
    for (int nt = 0; nt < 8; ++nt)
        #pragma unroll
        for (int mt = 0; mt < 2; ++mt)
            #pragma unroll
            for (int j = 0; j < 4; ++j) acc[nt][mt][j] = 0.f;

    #pragma unroll
    for (int kc = 0; kc < 12; ++kc) {
        if (kc < 11) cpa_wait1(); else cpa_wait0();
        __syncthreads();
        const uint32_t sa  = sb + ((kc & 1) ? K2A1 : K2A0);
        const uint32_t sbb = sb + ((kc & 1) ? K2B1 : K2B0);
        #pragma unroll
        for (int kk = 0; kk < 4; ++kk) {
            uint32_t a[2][4];
            #pragma unroll
            for (int mt = 0; mt < 2; ++mt)
                ldsm_x4(a[mt][0], a[mt][1], a[mt][2], a[mt][3],
                        sa + apat + mt * (16 * RS) + kk * 32);
            #pragma unroll
            for (int nt2 = 0; nt2 < 4; ++nt2) {
                uint32_t b0, b1, b2, b3;
                ldsm_x4(b0, b1, b2, b3, sbb + bpat + nt2 * (16 * RS) + kk * 32);
                #pragma unroll
                for (int mt = 0; mt < 2; ++mt) {
                    mma16816(acc[2*nt2    ][mt], a[mt][0], a[mt][1], a[mt][2], a[mt][3], b0, b1);
                    mma16816(acc[2*nt2 + 1][mt], a[mt][0], a[mt][1], a[mt][2], a[mt][3], b2, b3);
                }
            }
        }
        if (kc < 10) {
            __syncthreads();
            k2_prefetch(kc + 2, sa, sbb, tid, rowBase);
            cpa_commit();
        }
    }
    __syncthreads();

    const float s = 1.f / (1.f + __expf(-temp[0]));
    const int gidr = lane >> 2, tig = lane & 3;

    #pragma unroll
    for (int nt = 0; nt < 8; ++nt)
        #pragma unroll
        for (int mt = 0; mt < 2; ++mt)
            #pragma unroll
            for (int j = 0; j < 4; ++j) {
                const int col = ncol + nt * 8 + 2 * tig + (j & 1);
                float v = acc[nt][mt][j] + __ldg(&g_c[col]);
                acc[nt][mt][j] = s * __expf(-__fsqrt_rn(fmaxf(v, 0.f)));
            }

    float rmax[2][2];
    #pragma unroll
    for (int mt = 0; mt < 2; ++mt)
        #pragma unroll
        for (int hf = 0; hf < 2; ++hf) {
            float m = -1e30f;
            #pragma unroll
            for (int nt = 0; nt < 8; ++nt) {
                m = fmaxf(m, acc[nt][mt][2*hf]);
                m = fmaxf(m, acc[nt][mt][2*hf + 1]);
            }
            m = fmaxf(m, __shfl_xor_sync(0xFFFFFFFFu, m, 1));
            m = fmaxf(m, __shfl_xor_sync(0xFFFFFFFFu, m, 2));
            if (tig == 0) scr[(mrow + mt * 16 + gidr + hf * 8) * 4 + wn] = m;
        }
    __syncthreads();
    #pragma unroll
    for (int mt = 0; mt < 2; ++mt)
        #pragma unroll
        for (int hf = 0; hf < 2; ++hf) {
            const float* p = &scr[(mrow + mt * 16 + gidr + hf * 8) * 4];
            rmax[mt][hf] = fmaxf(fmaxf(p[0], p[1]), fmaxf(p[2], p[3]));
        }
    __syncthreads();

    float rsum[2][2];
    #pragma unroll
    for (int mt = 0; mt < 2; ++mt)
        #pragma unroll
        for (int hf = 0; hf < 2; ++hf) {
            float sm = 0.f;
            #pragma unroll
            for (int nt = 0; nt < 8; ++nt) {
                acc[nt][mt][2*hf]     = __expf(acc[nt][mt][2*hf]     - rmax[mt][hf]);
                acc[nt][mt][2*hf + 1] = __expf(acc[nt][mt][2*hf + 1] - rmax[mt][hf]);
                sm += acc[nt][mt][2*hf] + acc[nt][mt][2*hf + 1];
            }
            sm += __shfl_xor_sync(0xFFFFFFFFu, sm, 1);
            sm += __shfl_xor_sync(0xFFFFFFFFu, sm, 2);
            if (tig == 0) scr[(mrow + mt * 16 + gidr + hf * 8) * 4 + wn] = sm;
        }
    __syncthreads();
    #pragma unroll
    for (int mt = 0; mt < 2; ++mt)
        #pragma unroll
        for (int hf = 0; hf < 2; ++hf) {
            const float* p = &scr[(mrow + mt * 16 + gidr + hf * 8) * 4];
            rsum[mt][hf] = 1.f / (p[0] + p[1] + p[2] + p[3]);
        }

    #pragma unroll
    for (int mt = 0; mt < 2; ++mt)
        #pragma unroll
        for (int hf = 0; hf < 2; ++hf) {
            const size_t grow = (size_t)(rowBase + mrow + mt * 16 + gidr + hf * 8);
            const float inv = rsum[mt][hf];
            #pragma unroll
            for (int nt = 0; nt < 8; ++nt) {
                const int col = ncol + nt * 8 + 2 * tig;
                const size_t idx = grow * NFORM + col;
                out[idx]     = g_dnnf[idx]     * acc[nt][mt][2*hf]     * inv;
                out[idx + 1] = g_dnnf[idx + 1] * acc[nt][mt][2*hf + 1] * inv;
            }
        }
}

// ---------------------------------------------------------------------------
extern "C" void kernel_launch(void* const* d_in, const int* in_sizes, int n_in,
                              void* d_out, int out_size) {
    const float* x     = (const float*)d_in[0];
    const float* w     = (const float*)d_in[1];
    const float* bias  = (const float*)d_in[2];
    const float* lm    = (const float*)d_in[3];
    const float* mu    = (const float*)d_in[4];
    const float* sigma = (const float*)d_in[5];
    const float* temp  = (const float*)d_in[6];
    float* out = (float*)d_out;

    cudaFuncSetAttribute(k1_tensor, cudaFuncAttributeMaxDynamicSharedMemorySize, K1_SMEM);
    cudaFuncSetAttribute(k2_fused,  cudaFuncAttributeMaxDynamicSharedMemorySize, K2_SMEM);

    k0_split_x<<<BATCH * DIM / (256 * 8), 256>>>(x);
    k0_split_w<<<NLIT / 64, 256>>>(w, lm);
    k0_precompute<<<NFORM, DIM>>>(mu, sigma);
    k1_tensor<<<dim3(32, 99), 256, K1_SMEM>>>(bias);
    k2_fused<<<BATCH / 64, 256, K2_SMEM>>>(temp, out);
}

// round 10
// speedup vs baseline: 1.3086x; 1.1406x over previous
#include <cuda_runtime.h>
#include <cuda_bf16.h>
#include <math.h>
#include <stdint.h>

#define BATCH      4096
#define DIM        128
#define NFORM      256
#define NLIT       10752

// ---------------------------------------------------------------------------
// Helpers (portable PTX only: ldmatrix / mma.sync / cp.async / cvt.rna.tf32)
// ---------------------------------------------------------------------------
__device__ __forceinline__ float ftanh(float v) {
    float r; asm("tanh.approx.f32 %0, %1;" : "=f"(r) : "f"(v)); return r;
}
__device__ __forceinline__ uint32_t smem_u32(const void* p) {
    uint32_t a;
    asm("{ .reg .u64 t; cvta.to.shared.u64 t, %1; cvt.u32.u64 %0, t; }" : "=r"(a) : "l"(p));
    return a;
}
__device__ __forceinline__ uint32_t rna_tf32(float v) {
    uint32_t r; asm("cvt.rna.tf32.f32 %0, %1;" : "=r"(r) : "f"(v)); return r;
}
__device__ __forceinline__ void ldsm_x4(uint32_t& r0, uint32_t& r1, uint32_t& r2, uint32_t& r3,
                                        uint32_t addr) {
    asm volatile("ldmatrix.sync.aligned.m8n8.x4.shared.b16 {%0,%1,%2,%3}, [%4];"
                 : "=r"(r0), "=r"(r1), "=r"(r2), "=r"(r3) : "r"(addr));
}
__device__ __forceinline__ void mma16816(float* c, uint32_t a0, uint32_t a1, uint32_t a2,
                                         uint32_t a3, uint32_t b0, uint32_t b1) {
    asm volatile("mma.sync.aligned.m16n8k16.row.col.f32.bf16.bf16.f32 "
                 "{%0,%1,%2,%3}, {%4,%5,%6,%7}, {%8,%9}, {%0,%1,%2,%3};"
                 : "+f"(c[0]), "+f"(c[1]), "+f"(c[2]), "+f"(c[3])
                 : "r"(a0), "r"(a1), "r"(a2), "r"(a3), "r"(b0), "r"(b1));
}
__device__ __forceinline__ void mma_tf32(float* c, uint4 a, uint32_t b0, uint32_t b1) {
    asm volatile("mma.sync.aligned.m16n8k8.row.col.f32.tf32.tf32.f32 "
                 "{%0,%1,%2,%3}, {%4,%5,%6,%7}, {%8,%9}, {%0,%1,%2,%3};"
                 : "+f"(c[0]), "+f"(c[1]), "+f"(c[2]), "+f"(c[3])
                 : "r"(a.x), "r"(a.y), "r"(a.z), "r"(a.w), "r"(b0), "r"(b1));
}
__device__ __forceinline__ void cpa16(uint32_t dst, const void* src, uint32_t srcsize) {
    asm volatile("cp.async.ca.shared.global [%0], [%1], 16, %2;"
                 :: "r"(dst), "l"(src), "r"(srcsize));
}
__device__ __forceinline__ void cpa_commit() { asm volatile("cp.async.commit_group;"); }
__device__ __forceinline__ void cpa_wait1()  { asm volatile("cp.async.wait_group 1;"); }
__device__ __forceinline__ void cpa_wait0()  { asm volatile("cp.async.wait_group 0;"); }

// ---------------------------------------------------------------------------
// Scratch (device globals)
// ---------------------------------------------------------------------------
__device__ float          g_dnnf[BATCH * NFORM];
__device__ float          g_c   [NFORM];
__device__ __nv_bfloat16  g_x_hi[BATCH * DIM];      // k2
__device__ __nv_bfloat16  g_x_lo[BATCH * DIM];
__device__ __nv_bfloat16  g_x2h [BATCH * DIM];
__device__ __nv_bfloat16  g_x2l [BATCH * DIM];
__device__ __nv_bfloat16  g_s2h [NFORM * DIM];
__device__ __nv_bfloat16  g_s2l [NFORM * DIM];
__device__ __nv_bfloat16  g_m2h [NFORM * DIM];
__device__ __nv_bfloat16  g_m2l [NFORM * DIM];
__device__ uint4          g_xa[32 * 4096];          // k1 A: tf32, fragment-permuted
__device__ uint4          g_wb[99 * 4096];          // k1 B: tf32, fragment-permuted

__device__ __forceinline__ void split1(float v, __nv_bfloat16& h, __nv_bfloat16& l) {
    h = __float2bfloat16(v);
    l = __float2bfloat16(v - __bfloat162float(h));
}
__device__ __forceinline__ void split2(float v0, float v1, uint32_t& hi, uint32_t& lo) {
    __nv_bfloat16 h0, l0, h1, l1;
    split1(v0, h0, l0); split1(v1, h1, l1);
    __nv_bfloat162 hh = __halves2bfloat162(h0, h1);
    __nv_bfloat162 ll = __halves2bfloat162(l0, l1);
    hi = *reinterpret_cast<uint32_t*>(&hh);
    lo = *reinterpret_cast<uint32_t*>(&ll);
}

// ---------------------------------------------------------------------------
// yy-tile decode (shared by k0_prep_wb and k1)
// ---------------------------------------------------------------------------
__device__ __forceinline__ void decode_tile(int yy, int& LF, int& nd, int& nf,
                                            int& f0g, int& lb0) {
    if (yy < 13)      { LF = 24; nd = 2; nf = (yy == 12) ? 4 : 5; f0g = 5 * yy;          lb0 = 120 * yy; }
    else if (yy < 35) { int t = yy - 13; LF = 36; nd = 3; nf = (t == 21) ? 1 : 3; f0g = 64  + 3 * t; lb0 = 1536 + 108 * t; }
    else if (yy < 67) { int t = yy - 35; LF = 48; nd = 4; nf = 2; f0g = 128 + 2 * t; lb0 = 3840 + 96 * t; }
    else              { int t = yy - 67; LF = 60; nd = 5; nf = 2; f0g = 192 + 2 * t; lb0 = 6912 + 120 * t; }
}

// ---------------------------------------------------------------------------
// K0a: c[f] + bf16 splits of sigma^2 / -2*mu*sigma^2   (k2)
// ---------------------------------------------------------------------------
__global__ void k0_precompute(const float* __restrict__ mu,
                              const float* __restrict__ sigma) {
    int f = blockIdx.x, k = threadIdx.x;
    float sg = sigma[f * DIM + k];
    float m  = mu[f * DIM + k];
    float s2 = sg * sg;
    float m2 = -2.f * m * s2;
    __nv_bfloat16 h, l;
    split1(s2, h, l); g_s2h[f * DIM + k] = h; g_s2l[f * DIM + k] = l;
    split1(m2, h, l); g_m2h[f * DIM + k] = h; g_m2l[f * DIM + k] = l;
    float cp = m * m * s2;
    #pragma unroll
    for (int off = 16; off > 0; off >>= 1)
        cp += __shfl_xor_sync(0xFFFFFFFFu, cp, off);
    __shared__ float red[4];
    if ((k & 31) == 0) red[k >> 5] = cp;
    __syncthreads();
    if (k == 0) g_c[f] = red[0] + red[1] + red[2] + red[3];
}

// ---------------------------------------------------------------------------
// K0b: split x and x^2 into bf16 hi/lo  (k2)
// ---------------------------------------------------------------------------
__global__ __launch_bounds__(256) void k0_split_x(const float* __restrict__ x) {
    int e = blockIdx.x * 256 + threadIdx.x;
    const float4* src = reinterpret_cast<const float4*>(x) + (size_t)e * 2;
    float4 a = src[0], b = src[1];
    float v[8] = {a.x, a.y, a.z, a.w, b.x, b.y, b.z, b.w};
    uint32_t hi[4], lo[4], qhi[4], qlo[4];
    #pragma unroll
    for (int p = 0; p < 4; ++p) {
        split2(v[2*p], v[2*p+1], hi[p], lo[p]);
        split2(v[2*p]*v[2*p], v[2*p+1]*v[2*p+1], qhi[p], qlo[p]);
    }
    reinterpret_cast<uint4*>(g_x_hi)[e] = make_uint4(hi[0], hi[1], hi[2], hi[3]);
    reinterpret_cast<uint4*>(g_x_lo)[e] = make_uint4(lo[0], lo[1], lo[2], lo[3]);
    reinterpret_cast<uint4*>(g_x2h)[e]  = make_uint4(qhi[0], qhi[1], qhi[2], qhi[3]);
    reinterpret_cast<uint4*>(g_x2l)[e]  = make_uint4(qlo[0], qlo[1], qlo[2], qlo[3]);
}

// ---------------------------------------------------------------------------
// K0c: x -> tf32(rna) fragment-permuted blob g_xa
//   layout: [rb(32)][kc(4)][wm(4)][mt(2)][ks(4)][lane(32)] x uint4
//   uint4 = { A(r,c), A(r+8,c), A(r,c+4), A(r+8,c+4) },
//   r = wm*32+mt*16+(lane>>2), c = kc*32+ks*8+(lane&3)
// ---------------------------------------------------------------------------
#define PREP_SMEM (128 * 132 * 4)
__global__ __launch_bounds__(256) void k0_prep_xa(const float* __restrict__ x) {
    extern __shared__ __align__(16) float xs[];          // [128][132]
    const int rb = blockIdx.x, tid = threadIdx.x;
    for (int e = tid; e < 128 * 32; e += 256) {
        int r = e >> 5, c4 = e & 31;
        float4 v = reinterpret_cast<const float4*>(x + (size_t)(rb * 128 + r) * DIM)[c4];
        xs[r * 132 + c4 * 4 + 0] = v.x;
        xs[r * 132 + c4 * 4 + 1] = v.y;
        xs[r * 132 + c4 * 4 + 2] = v.z;
        xs[r * 132 + c4 * 4 + 3] = v.w;
    }
    __syncthreads();
    #pragma unroll
    for (int i = 0; i < 16; ++i) {
        int o = i * 256 + tid;
        int lane = o & 31, ks = (o >> 5) & 3, mt = (o >> 7) & 1;
        int wm = (o >> 8) & 3, kc = (o >> 10) & 3;
        int r = wm * 32 + mt * 16 + (lane >> 2);
        int c = kc * 32 + ks * 8 + (lane & 3);
        g_xa[(size_t)rb * 4096 + o] =
            make_uint4(rna_tf32(xs[r * 132 + c]),       rna_tf32(xs[(r + 8) * 132 + c]),
                       rna_tf32(xs[r * 132 + c + 4]),   rna_tf32(xs[(r + 8) * 132 + c + 4]));
    }
}

// ---------------------------------------------------------------------------
// K0d: masked W -> tf32(rna) fragment-permuted blob g_wb (per yy-tile, 0-pad)
//   layout: [yy(99)][kc(4)][wn(2)][ks(4)][p(4)][lane(32)] x uint4
//   uint4 = { B(k,n), B(k+4,n), B(k,n+8), B(k+4,n+8) },
//   n = wn*64+p*16+(lane>>2), k = kc*32+ks*8+(lane&3)
// ---------------------------------------------------------------------------
__global__ __launch_bounds__(256) void k0_prep_wb(const float* __restrict__ w,
                                                  const float* __restrict__ lm) {
    extern __shared__ __align__(16) float ws[];          // [128 k][132 n]
    const int yy = blockIdx.x, tid = threadIdx.x;
    int LF, nd, nf, f0g, lb0;
    decode_tile(yy, LF, nd, nf, f0g, lb0);
    const int LIVE = nf * LF;
    for (int e = tid; e < 128 * 128; e += 256) {
        int k = e >> 7, j = e & 127;
        float val = 0.f;
        if (j < LIVE) {
            int f = f0g + j / LF;
            float mk = (fabsf(lm[k * NFORM + f]) > 1.0f) ? 1.0f : 0.0f;
            val = w[(size_t)k * NLIT + lb0 + j] * mk;
        }
        ws[k * 132 + j] = val;
    }
    __syncthreads();
    #pragma unroll
    for (int i = 0; i < 16; ++i) {
        int o = i * 256 + tid;
        int lane = o & 31, p = (o >> 5) & 3, ks = (o >> 7) & 3;
        int wn = (o >> 9) & 1, kc = (o >> 10) & 3;
        int n = wn * 64 + p * 16 + (lane >> 2);
        int k = kc * 32 + ks * 8 + (lane & 3);
        g_wb[(size_t)yy * 4096 + o] =
            make_uint4(rna_tf32(ws[k * 132 + n]),       rna_tf32(ws[(k + 4) * 132 + n]),
                       rna_tf32(ws[k * 132 + n + 8]),   rna_tf32(ws[(k + 4) * 132 + n + 8]));
    }
}

// ---------------------------------------------------------------------------
// K1: single-pass TF32 literal GEMM (K=128) + fused tanh/segmented reduce
//   CTA M128 x N128, 8 warps (4M x 2N, warp tile M32xN64), 4 K32 chunks,
//   2-stage cp.async pipeline, fragment loads are contiguous LDS.128.
// ---------------------------------------------------------------------------
#define K1_SA0   1024
#define K1_SA1   (K1_SA0 + 16384)
#define K1_SB0   (K1_SA1 + 16384)
#define K1_SB1   (K1_SB0 + 16384)
#define K1_SMEM  69632

__device__ __forceinline__ void k1_prefetch(int kc, uint32_t sa, uint32_t sbb,
                                            int tid, int rb, int yy) {
    const uint4* asrc = g_xa + (size_t)rb * 4096 + kc * 1024;
    const uint4* bsrc = g_wb + (size_t)yy * 4096 + kc * 1024;
    #pragma unroll
    for (int i = 0; i < 4; ++i) {
        int e = tid + i * 256;
        cpa16(sa  + e * 16, asrc + e, 16);
        cpa16(sbb + e * 16, bsrc + e, 16);
    }
}

__global__ __launch_bounds__(256, 2) void k1_tensor(const float* __restrict__ bias) {
    extern __shared__ __align__(1024) char smem[];
    const uint32_t sb = smem_u32(smem);
    float* bs = reinterpret_cast<float*>(smem);          // 128 floats @ 0

    const int tid  = threadIdx.x;
    const int wid  = tid >> 5;
    const int lane = tid & 31;
    const int rb   = blockIdx.x;
    const int yy   = blockIdx.y;
    const int rowBase = rb * 128;

    int LF, nd, nf, f0g, lb0;
    decode_tile(yy, LF, nd, nf, f0g, lb0);
    const int LIVE = nf * LF;

    if (tid < 128) bs[tid] = (tid < LIVE) ? bias[lb0 + tid] : 0.f;

    k1_prefetch(0, sb + K1_SA0, sb + K1_SB0, tid, rb, yy);
    cpa_commit();
    k1_prefetch(1, sb + K1_SA1, sb + K1_SB1, tid, rb, yy);
    cpa_commit();

    const int wm = wid & 3;                  // M warp row (0..3) -> mrow = wm*32
    const int wn = wid >> 2;                 // N warp col (0..1) -> ncol = wn*64
    const int mrow = wm * 32, ncol = wn * 64;
    // stage-relative fragment addresses (all contiguous 16B per lane)
    const uint32_t aoff = (uint32_t)(wm * 4096 + lane * 16);     // + mt*2048 + ks*512
    const uint32_t boff = (uint32_t)(wn * 8192 + lane * 16);     // + ks*2048 + p*512

    float acc[8][2][4];
    #pragma unroll
    for (int nt = 0; nt < 8; ++nt)
        #pragma unroll
        for (int mt = 0; mt < 2; ++mt)
            #pragma unroll
            for (int j = 0; j < 4; ++j) acc[nt][mt][j] = 0.f;

    #pragma unroll
    for (int kc = 0; kc < 4; ++kc) {
        if (kc < 3) cpa_wait1(); else cpa_wait0();
        __syncthreads();
        const char* sa  = smem + ((kc & 1) ? K1_SA1 : K1_SA0);
        const char* sbb = smem + ((kc & 1) ? K1_SB1 : K1_SB0);
        #pragma unroll
        for (int ks = 0; ks < 4; ++ks) {
            uint4 av[2];
            av[0] = *reinterpret_cast<const uint4*>(sa + aoff + ks * 512);
            av[1] = *reinterpret_cast<const uint4*>(sa + aoff + 2048 + ks * 512);
            #pragma unroll
            for (int p = 0; p < 4; ++p) {
                uint4 bv = *reinterpret_cast<const uint4*>(sbb + boff + ks * 2048 + p * 512);
                #pragma unroll
                for (int mt = 0; mt < 2; ++mt) {
                    mma_tf32(acc[2*p    ][mt], av[mt], bv.x, bv.y);
                    mma_tf32(acc[2*p + 1][mt], av[mt], bv.z, bv.w);
                }
            }
        }
        if (kc < 2) {
            __syncthreads();
            k1_prefetch(kc + 2, sb + ((kc & 1) ? K1_SA1 : K1_SA0),
                        sb + ((kc & 1) ? K1_SB1 : K1_SB0), tid, rb, yy);
            cpa_commit();
        }
    }
    __syncthreads();

    // ---- tanh(literal) -> ct[128][130] (overlays stage smem) ----
    float* ct = reinterpret_cast<float*>(smem + K1_SA0);
    {
        const int gidr = lane >> 2, tig = lane & 3;
        #pragma unroll
        for (int nt = 0; nt < 8; ++nt) {
            const int c0 = ncol + nt * 8 + 2 * tig;
            #pragma unroll
            for (int mt = 0; mt < 2; ++mt) {
                const int r0 = mrow + mt * 16 + gidr;
                ct[r0 * 130 + c0]           = ftanh(acc[nt][mt][0] + bs[c0]);
                ct[r0 * 130 + c0 + 1]       = ftanh(acc[nt][mt][1] + bs[c0 + 1]);
                ct[(r0 + 8) * 130 + c0]     = ftanh(acc[nt][mt][2] + bs[c0]);
                ct[(r0 + 8) * 130 + c0 + 1] = ftanh(acc[nt][mt][3] + bs[c0 + 1]);
            }
        }
    }
    __syncthreads();

    // ---- segmented reduce: nd conjs each of depth 2/4/6 -> formula ----
    for (int task = tid; task < 128 * nf; task += 256) {
        const int row = task & 127;
        const int fi  = task >> 7;
        const float* cr = &ct[row * 130 + fi * LF];
        float fs = 0.f;
        int off = 0;
        #pragma unroll
        for (int dd = 0; dd < 3; ++dd) {
            const int d = 2 + 2 * dd;
            for (int c = 0; c < nd; ++c) {
                float sA = 0.f;
                #pragma unroll
                for (int u = 0; u < 6; ++u)
                    if (u < d) sA += cr[off + u];
                fs += ftanh(sA - (float)d + 1.5f);
                off += d;
            }
        }
        g_dnnf[(size_t)(rowBase + row) * NFORM + f0g + fi] =
            ftanh(fs + 3.0f * (float)nd - 1.5f);
    }
}

// ---------------------------------------------------------------------------
// K2 fused: v GEMM (bf16 3-pass, virtual K=768) + loc + softmax + mul -> out
// ---------------------------------------------------------------------------
#define RS     144
#define K2A0   0
#define K2A1   (K2A0 + 64 * RS)
#define K2B0   (K2A1 + 64 * RS)
#define K2B1   (K2B0 + 256 * RS)
#define K2SCR  (K2B1 + 256 * RS)
#define K2_SMEM (K2SCR + 64 * 4 * 4)

__device__ __forceinline__ void k2_prefetch(int kc, uint32_t sa, uint32_t sbb,
                                            int tid, int rowBase) {
    const int p = kc >> 1, koff = (kc & 1) * 64;
    const __nv_bfloat16* asrc =
        (p == 0 || p == 2) ? g_x2h : (p == 1) ? g_x2l :
        (p == 3 || p == 5) ? g_x_hi : g_x_lo;
    const __nv_bfloat16* bsrc =
        (p <= 1) ? g_s2h : (p == 2) ? g_s2l : (p <= 4) ? g_m2h : g_m2l;
    #pragma unroll
    for (int i = 0; i < 2; ++i) {
        int e = tid + i * 256;
        int r = e >> 3, ch = e & 7;
        cpa16(sa + r * RS + ch * 16,
              asrc + (size_t)(rowBase + r) * DIM + koff + ch * 8, 16);
    }
    #pragma unroll
    for (int i = 0; i < 8; ++i) {
        int e = tid + i * 256;
        int n = e >> 3, ch = e & 7;
        cpa16(sbb + n * RS + ch * 16, bsrc + (size_t)n * DIM + koff + ch * 8, 16);
    }
}

__global__ __launch_bounds__(256) void k2_fused(const float* __restrict__ temp,
                                                float* __restrict__ out) {
    extern __shared__ __align__(1024) char smem[];
    const uint32_t sb = smem_u32(smem);
    float* scr = reinterpret_cast<float*>(smem + K2SCR);

    const int tid     = threadIdx.x;
    const int wid     = tid >> 5;
    const int lane    = tid & 31;
    const int rowBase = blockIdx.x * 64;

    k2_prefetch(0, sb + K2A0, sb + K2B0, tid, rowBase);
    cpa_commit();
    k2_prefetch(1, sb + K2A1, sb + K2B1, tid, rowBase);
    cpa_commit();

    const int wm = wid & 1, wn = wid >> 1;
    const int mrow = wm * 32, ncol = wn * 64;
    const uint32_t apat = (uint32_t)((mrow + (lane & 15)) * RS + (lane >> 4) * 16);
    const uint32_t bpat = (uint32_t)((ncol + (lane & 7) + ((lane >> 4) & 1) * 8) * RS +
                                     ((lane >> 3) & 1) * 16);

    float acc[8][2][4];
    #pragma unroll
    for (int nt = 0; nt < 8; ++nt)
        #pragma unroll
        for (int mt = 0; mt < 2; ++mt)
            #pragma unroll
            for (int j = 0; j < 4; ++j) acc[nt][mt][j] = 0.f;

    #pragma unroll
    for (int kc = 0; kc < 12; ++kc) {
        if (kc < 11) cpa_wait1(); else cpa_wait0();
        __syncthreads();
        const uint32_t sa  = sb + ((kc & 1) ? K2A1 : K2A0);
        const uint32_t sbb = sb + ((kc & 1) ? K2B1 : K2B0);
        #pragma unroll
        for (int kk = 0; kk < 4; ++kk) {
            uint32_t a[2][4];
            #pragma unroll
            for (int mt = 0; mt < 2; ++mt)
                ldsm_x4(a[mt][0], a[mt][1], a[mt][2], a[mt][3],
                        sa + apat + mt * (16 * RS) + kk * 32);
            #pragma unroll
            for (int nt2 = 0; nt2 < 4; ++nt2) {
                uint32_t b0, b1, b2, b3;
                ldsm_x4(b0, b1, b2, b3, sbb + bpat + nt2 * (16 * RS) + kk * 32);
                #pragma unroll
                for (int mt = 0; mt < 2; ++mt) {
                    mma16816(acc[2*nt2    ][mt], a[mt][0], a[mt][1], a[mt][2], a[mt][3], b0, b1);
                    mma16816(acc[2*nt2 + 1][mt], a[mt][0], a[mt][1], a[mt][2], a[mt][3], b2, b3);
                }
            }
        }
        if (kc < 10) {
            __syncthreads();
            k2_prefetch(kc + 2, sa, sbb, tid, rowBase);
            cpa_commit();
        }
    }
    __syncthreads();

    const float s = 1.f / (1.f + __expf(-temp[0]));
    const int gidr = lane >> 2, tig = lane & 3;

    #pragma unroll
    for (int nt = 0; nt < 8; ++nt)
        #pragma unroll
        for (int mt = 0; mt < 2; ++mt)
            #pragma unroll
            for (int j = 0; j < 4; ++j) {
                const int col = ncol + nt * 8 + 2 * tig + (j & 1);
                float v = acc[nt][mt][j] + __ldg(&g_c[col]);
                acc[nt][mt][j] = s * __expf(-__fsqrt_rn(fmaxf(v, 0.f)));
            }

    float rmax[2][2];
    #pragma unroll
    for (int mt = 0; mt < 2; ++mt)
        #pragma unroll
        for (int hf = 0; hf < 2; ++hf) {
            float m = -1e30f;
            #pragma unroll
            for (int nt = 0; nt < 8; ++nt) {
                m = fmaxf(m, acc[nt][mt][2*hf]);
                m = fmaxf(m, acc[nt][mt][2*hf + 1]);
            }
            m = fmaxf(m, __shfl_xor_sync(0xFFFFFFFFu, m, 1));
            m = fmaxf(m, __shfl_xor_sync(0xFFFFFFFFu, m, 2));
            if (tig == 0) scr[(mrow + mt * 16 + gidr + hf * 8) * 4 + wn] = m;
        }
    __syncthreads();
    #pragma unroll
    for (int mt = 0; mt < 2; ++mt)
        #pragma unroll
        for (int hf = 0; hf < 2; ++hf) {
            const float* p = &scr[(mrow + mt * 16 + gidr + hf * 8) * 4];
            rmax[mt][hf] = fmaxf(fmaxf(p[0], p[1]), fmaxf(p[2], p[3]));
        }
    __syncthreads();

    float rsum[2][2];
    #pragma unroll
    for (int mt = 0; mt < 2; ++mt)
        #pragma unroll
        for (int hf = 0; hf < 2; ++hf) {
            float sm = 0.f;
            #pragma unroll
            for (int nt = 0; nt < 8; ++nt) {
                acc[nt][mt][2*hf]     = __expf(acc[nt][mt][2*hf]     - rmax[mt][hf]);
                acc[nt][mt][2*hf + 1] = __expf(acc[nt][mt][2*hf + 1] - rmax[mt][hf]);
                sm += acc[nt][mt][2*hf] + acc[nt][mt][2*hf + 1];
            }
            sm += __shfl_xor_sync(0xFFFFFFFFu, sm, 1);
            sm += __shfl_xor_sync(0xFFFFFFFFu, sm, 2);
            if (tig == 0) scr[(mrow + mt * 16 + gidr + hf * 8) * 4 + wn] = sm;
        }
    __syncthreads();
    #pragma unroll
    for (int mt = 0; mt < 2; ++mt)
        #pragma unroll
        for (int hf = 0; hf < 2; ++hf) {
            const float* p = &scr[(mrow + mt * 16 + gidr + hf * 8) * 4];
            rsum[mt][hf] = 1.f / (p[0] + p[1] + p[2] + p[3]);
        }

    #pragma unroll
    for (int mt = 0; mt < 2; ++mt)
        #pragma unroll
        for (int hf = 0; hf < 2; ++hf) {
            const size_t grow = (size_t)(rowBase + mrow + mt * 16 + gidr + hf * 8);
            const float inv = rsum[mt][hf];
            #pragma unroll
            for (int nt = 0; nt < 8; ++nt) {
                const int col = ncol + nt * 8 + 2 * tig;
                const size_t idx = grow * NFORM + col;
                out[idx]     = g_dnnf[idx]     * acc[nt][mt][2*hf]     * inv;
                out[idx + 1] = g_dnnf[idx + 1] * acc[nt][mt][2*hf + 1] * inv;
            }
        }
}

// ---------------------------------------------------------------------------
extern "C" void kernel_launch(void* const* d_in, const int* in_sizes, int n_in,
                              void* d_out, int out_size) {
    const float* x     = (const float*)d_in[0];
    const float* w     = (const float*)d_in[1];
    const float* bias  = (const float*)d_in[2];
    const float* lm    = (const float*)d_in[3];
    const float* mu    = (const float*)d_in[4];
    const float* sigma = (const float*)d_in[5];
    const float* temp  = (const float*)d_in[6];
    float* out = (float*)d_out;

    cudaFuncSetAttribute(k0_prep_xa, cudaFuncAttributeMaxDynamicSharedMemorySize, PREP_SMEM);
    cudaFuncSetAttribute(k0_prep_wb, cudaFuncAttributeMaxDynamicSharedMemorySize, PREP_SMEM);
    cudaFuncSetAttribute(k1_tensor,  cudaFuncAttributeMaxDynamicSharedMemorySize, K1_SMEM);
    cudaFuncSetAttribute(k2_fused,   cudaFuncAttributeMaxDynamicSharedMemorySize, K2_SMEM);

    k0_split_x<<<BATCH * DIM / (256 * 8), 256>>>(x);
    k0_prep_xa<<<32, 256, PREP_SMEM>>>(x);
    k0_prep_wb<<<99, 256, PREP_SMEM>>>(w, lm);
    k0_precompute<<<NFORM, DIM>>>(mu, sigma);
    k1_tensor<<<dim3(32, 99), 256, K1_SMEM>>>(bias);
    k2_fused<<<BATCH / 64, 256, K2_SMEM>>>(temp, out);
}

// round 11
// speedup vs baseline: 1.3419x; 1.0254x over previous
#include <cuda_runtime.h>
#include <cuda_bf16.h>
#include <math.h>
#include <stdint.h>

#define BATCH      4096
#define DIM        128
#define NFORM      256
#define NLIT       10752

// ---------------------------------------------------------------------------
// Helpers (portable PTX only: mma.sync / cp.async / cvt.rna.tf32)
// ---------------------------------------------------------------------------
__device__ __forceinline__ float ftanh(float v) {
    float r; asm("tanh.approx.f32 %0, %1;" : "=f"(r) : "f"(v)); return r;
}
__device__ __forceinline__ uint32_t smem_u32(const void* p) {
    uint32_t a;
    asm("{ .reg .u64 t; cvta.to.shared.u64 t, %1; cvt.u32.u64 %0, t; }" : "=r"(a) : "l"(p));
    return a;
}
__device__ __forceinline__ uint32_t rna_tf32(float v) {
    uint32_t r; asm("cvt.rna.tf32.f32 %0, %1;" : "=r"(r) : "f"(v)); return r;
}
__device__ __forceinline__ void mma_tf32(float* c, uint4 a, uint32_t b0, uint32_t b1) {
    asm volatile("mma.sync.aligned.m16n8k8.row.col.f32.tf32.tf32.f32 "
                 "{%0,%1,%2,%3}, {%4,%5,%6,%7}, {%8,%9}, {%0,%1,%2,%3};"
                 : "+f"(c[0]), "+f"(c[1]), "+f"(c[2]), "+f"(c[3])
                 : "r"(a.x), "r"(a.y), "r"(a.z), "r"(a.w), "r"(b0), "r"(b1));
}
__device__ __forceinline__ void cpa16(uint32_t dst, const void* src) {
    asm volatile("cp.async.ca.shared.global [%0], [%1], 16;" :: "r"(dst), "l"(src));
}
__device__ __forceinline__ void cpa_commit() { asm volatile("cp.async.commit_group;"); }
__device__ __forceinline__ void cpa_wait1()  { asm volatile("cp.async.wait_group 1;"); }
__device__ __forceinline__ void cpa_wait0()  { asm volatile("cp.async.wait_group 0;"); }

// ---------------------------------------------------------------------------
// Scratch (device globals)
// ---------------------------------------------------------------------------
__device__ float g_dnnf[BATCH * NFORM];
__device__ float g_c   [NFORM];
__device__ uint4 g_xa [32 * 4096];      // k1 A: tf32 fragments, per 128-row block
__device__ uint4 g_wb [99 * 4096];      // k1 B: tf32 fragments, per yy-tile
__device__ uint4 g_xa2[128 * 2048];     // k2 A: [x^2 || x], per 32-row block
__device__ uint4 g_b2 [8 * 2048];       // k2 B: [sigma^2 ; -2 mu sigma^2]

// ---------------------------------------------------------------------------
// yy-tile decode (k1)
// ---------------------------------------------------------------------------
__device__ __forceinline__ void decode_tile(int yy, int& LF, int& nd, int& nf,
                                            int& f0g, int& lb0) {
    if (yy < 13)      { LF = 24; nd = 2; nf = (yy == 12) ? 4 : 5; f0g = 5 * yy;          lb0 = 120 * yy; }
    else if (yy < 35) { int t = yy - 13; LF = 36; nd = 3; nf = (t == 21) ? 1 : 3; f0g = 64  + 3 * t; lb0 = 1536 + 108 * t; }
    else if (yy < 67) { int t = yy - 35; LF = 48; nd = 4; nf = 2; f0g = 128 + 2 * t; lb0 = 3840 + 96 * t; }
    else              { int t = yy - 67; LF = 60; nd = 5; nf = 2; f0g = 192 + 2 * t; lb0 = 6912 + 120 * t; }
}

// ---------------------------------------------------------------------------
// K0a: x -> k1 A blob (g_xa) + k2 A blob (g_xa2), tf32(rna) fragment-permuted
//   g_xa : [rb(32)][kc(4)][wm(4)][mt(2)][ks(4)][lane] {A(r,c),A(r+8,c),A(r,c+4),A(r+8,c+4)}
//   g_xa2: [xb(128)][kc(8)][wm(2)][ks(4)][lane]  c<128 -> x^2, else x
// ---------------------------------------------------------------------------
#define PREP_SMEM (128 * 132 * 4)
__global__ __launch_bounds__(256) void k0_prep_xa(const float* __restrict__ x) {
    extern __shared__ __align__(16) float xs[];          // [128][132]
    const int rb = blockIdx.x, tid = threadIdx.x;
    for (int e = tid; e < 128 * 32; e += 256) {
        int r = e >> 5, c4 = e & 31;
        float4 v = reinterpret_cast<const float4*>(x + (size_t)(rb * 128 + r) * DIM)[c4];
        xs[r * 132 + c4 * 4 + 0] = v.x;
        xs[r * 132 + c4 * 4 + 1] = v.y;
        xs[r * 132 + c4 * 4 + 2] = v.z;
        xs[r * 132 + c4 * 4 + 3] = v.w;
    }
    __syncthreads();
    // k1 blob
    #pragma unroll
    for (int i = 0; i < 16; ++i) {
        int o = i * 256 + tid;
        int lane = o & 31, ks = (o >> 5) & 3, mt = (o >> 7) & 1;
        int wm = (o >> 8) & 3, kc = (o >> 10) & 3;
        int r = wm * 32 + mt * 16 + (lane >> 2);
        int c = kc * 32 + ks * 8 + (lane & 3);
        g_xa[(size_t)rb * 4096 + o] =
            make_uint4(rna_tf32(xs[r * 132 + c]),     rna_tf32(xs[(r + 8) * 132 + c]),
                       rna_tf32(xs[r * 132 + c + 4]), rna_tf32(xs[(r + 8) * 132 + c + 4]));
    }
    // k2 blob: 4 sub-blocks of 32 rows
    #pragma unroll
    for (int i = 0; i < 32; ++i) {
        int o = i * 256 + tid;                            // 8192 entries
        int lane = o & 31, ks = (o >> 5) & 3, wm = (o >> 7) & 1;
        int kc = (o >> 8) & 7, sub = (o >> 11) & 3;
        int r = sub * 32 + wm * 16 + (lane >> 2);
        int c = kc * 32 + ks * 8 + (lane & 3);
        float v0, v1, v2, v3;
        if (c < 128) {
            float a = xs[r * 132 + c],      b = xs[(r + 8) * 132 + c];
            float d = xs[r * 132 + c + 4],  e = xs[(r + 8) * 132 + c + 4];
            v0 = a * a; v1 = b * b; v2 = d * d; v3 = e * e;
        } else {
            int cc = c - 128;
            v0 = xs[r * 132 + cc];     v1 = xs[(r + 8) * 132 + cc];
            v2 = xs[r * 132 + cc + 4]; v3 = xs[(r + 8) * 132 + cc + 4];
        }
        g_xa2[(size_t)(rb * 4 + sub) * 2048 + (o & 2047)] =
            make_uint4(rna_tf32(v0), rna_tf32(v1), rna_tf32(v2), rna_tf32(v3));
    }
}

// ---------------------------------------------------------------------------
// K0b: masked W -> k1 B blob (g_wb), per yy-tile, zero-padded
// ---------------------------------------------------------------------------
__global__ __launch_bounds__(256) void k0_prep_wb(const float* __restrict__ w,
                                                  const float* __restrict__ lm) {
    extern __shared__ __align__(16) float ws[];          // [128 k][132 n]
    const int yy = blockIdx.x, tid = threadIdx.x;
    int LF, nd, nf, f0g, lb0;
    decode_tile(yy, LF, nd, nf, f0g, lb0);
    const int LIVE = nf * LF;
    for (int e = tid; e < 128 * 128; e += 256) {
        int k = e >> 7, j = e & 127;
        float val = 0.f;
        if (j < LIVE) {
            int f = f0g + j / LF;
            float mk = (fabsf(lm[k * NFORM + f]) > 1.0f) ? 1.0f : 0.0f;
            val = w[(size_t)k * NLIT + lb0 + j] * mk;
        }
        ws[k * 132 + j] = val;
    }
    __syncthreads();
    #pragma unroll
    for (int i = 0; i < 16; ++i) {
        int o = i * 256 + tid;
        int lane = o & 31, p = (o >> 5) & 3, ks = (o >> 7) & 3;
        int wn = (o >> 9) & 1, kc = (o >> 10) & 3;
        int n = wn * 64 + p * 16 + (lane >> 2);
        int k = kc * 32 + ks * 8 + (lane & 3);
        g_wb[(size_t)yy * 4096 + o] =
            make_uint4(rna_tf32(ws[k * 132 + n]),     rna_tf32(ws[(k + 4) * 132 + n]),
                       rna_tf32(ws[k * 132 + n + 8]), rna_tf32(ws[(k + 4) * 132 + n + 8]));
    }
}

// ---------------------------------------------------------------------------
// K0c: k2 B blob (g_b2) + c[f].  grid = 9: blocks 0..7 -> kc, block 8 -> c[f]
// ---------------------------------------------------------------------------
__device__ __forceinline__ float b2val(const float* mu, const float* sg, int k, int n) {
    if (k < 128) { float s = sg[n * DIM + k]; return s * s; }
    int kk = k - 128;
    float s = sg[n * DIM + kk];
    return -2.f * mu[n * DIM + kk] * s * s;
}
__global__ __launch_bounds__(256) void k0_prep_b2c(const float* __restrict__ mu,
                                                   const float* __restrict__ sigma) {
    const int b = blockIdx.x, tid = threadIdx.x;
    if (b < 8) {
        #pragma unroll
        for (int i = 0; i < 8; ++i) {
            int o = i * 256 + tid;                        // 2048 entries
            int lane = o & 31, p = (o >> 5) & 3, ks = (o >> 7) & 3, wn = (o >> 9) & 3;
            int n = wn * 64 + p * 16 + (lane >> 2);
            int k = b * 32 + ks * 8 + (lane & 3);
            g_b2[(size_t)b * 2048 + o] =
                make_uint4(rna_tf32(b2val(mu, sigma, k,     n)),
                           rna_tf32(b2val(mu, sigma, k + 4, n)),
                           rna_tf32(b2val(mu, sigma, k,     n + 8)),
                           rna_tf32(b2val(mu, sigma, k + 4, n + 8)));
        }
    } else {
        int f = tid;                                      // 256 threads, 1 formula each
        const float4* m4 = reinterpret_cast<const float4*>(mu + f * DIM);
        const float4* s4 = reinterpret_cast<const float4*>(sigma + f * DIM);
        float c = 0.f;
        #pragma unroll 8
        for (int i = 0; i < 32; ++i) {
            float4 m = m4[i], s = s4[i];
            c += m.x * m.x * s.x * s.x + m.y * m.y * s.y * s.y
               + m.z * m.z * s.z * s.z + m.w * m.w * s.w * s.w;
        }
        g_c[f] = c;
    }
}

// ---------------------------------------------------------------------------
// K1: single-pass TF32 literal GEMM (K=128) + fused tanh/segmented reduce
//   CTA M128 x N128, 8 warps (4M x 2N), 4 K32 chunks, 3-stage cp.async.
// ---------------------------------------------------------------------------
#define K1_ST(s) (1024 + (s) * 32768)       // A 16KB @ +0, B 16KB @ +16384
#define K1_SMEM  (1024 + 3 * 32768)         // 99328

__device__ __forceinline__ void k1_prefetch(int kc, uint32_t st, int tid, int rb, int yy) {
    const uint4* asrc = g_xa + (size_t)rb * 4096 + kc * 1024;
    const uint4* bsrc = g_wb + (size_t)yy * 4096 + kc * 1024;
    #pragma unroll
    for (int i = 0; i < 4; ++i) {
        int e = tid + i * 256;
        cpa16(st + e * 16,         asrc + e);
        cpa16(st + 16384 + e * 16, bsrc + e);
    }
}

__global__ __launch_bounds__(256, 2) void k1_tensor(const float* __restrict__ bias) {
    extern __shared__ __align__(1024) char smem[];
    const uint32_t sb = smem_u32(smem);
    float* bs = reinterpret_cast<float*>(smem);          // 128 floats @ 0

    const int tid  = threadIdx.x;
    const int wid  = tid >> 5;
    const int lane = tid & 31;
    const int rb   = blockIdx.x;
    const int yy   = blockIdx.y;
    const int rowBase = rb * 128;

    int LF, nd, nf, f0g, lb0;
    decode_tile(yy, LF, nd, nf, f0g, lb0);
    const int LIVE = nf * LF;

    if (tid < 128) bs[tid] = (tid < LIVE) ? bias[lb0 + tid] : 0.f;

    k1_prefetch(0, sb + K1_ST(0), tid, rb, yy);
    cpa_commit();
    k1_prefetch(1, sb + K1_ST(1), tid, rb, yy);
    cpa_commit();

    const int wm = wid & 3, wn = wid >> 2;
    const int mrow = wm * 32, ncol = wn * 64;
    const uint32_t aoff = (uint32_t)(wm * 4096 + lane * 16);     // + mt*2048 + ks*512
    const uint32_t boff = (uint32_t)(16384 + wn * 8192 + lane * 16); // + ks*2048 + p*512

    float acc[8][2][4];
    #pragma unroll
    for (int nt = 0; nt < 8; ++nt)
        #pragma unroll
        for (int mt = 0; mt < 2; ++mt)
            #pragma unroll
            for (int j = 0; j < 4; ++j) acc[nt][mt][j] = 0.f;

    #pragma unroll
    for (int kc = 0; kc < 4; ++kc) {
        if (kc < 3) cpa_wait1(); else cpa_wait0();
        __syncthreads();
        if (kc < 2) {                        // prefetch into stage freed last iter
            k1_prefetch(kc + 2, sb + K1_ST((kc + 2) % 3), tid, rb, yy);
            cpa_commit();
        }
        const char* st = smem + K1_ST(kc % 3);
        #pragma unroll
        for (int ks = 0; ks < 4; ++ks) {
            uint4 av[2];
            av[0] = *reinterpret_cast<const uint4*>(st + aoff + ks * 512);
            av[1] = *reinterpret_cast<const uint4*>(st + aoff + 2048 + ks * 512);
            #pragma unroll
            for (int p = 0; p < 4; ++p) {
                uint4 bv = *reinterpret_cast<const uint4*>(st + boff + ks * 2048 + p * 512);
                #pragma unroll
                for (int mt = 0; mt < 2; ++mt) {
                    mma_tf32(acc[2*p    ][mt], av[mt], bv.x, bv.y);
                    mma_tf32(acc[2*p + 1][mt], av[mt], bv.z, bv.w);
                }
            }
        }
    }
    __syncthreads();

    // ---- tanh(literal) -> ct[128][130] (overlays stage smem) ----
    float* ct = reinterpret_cast<float*>(smem + K1_ST(0));
    {
        const int gidr = lane >> 2, tig = lane & 3;
        #pragma unroll
        for (int nt = 0; nt < 8; ++nt) {
            const int c0 = ncol + nt * 8 + 2 * tig;
            #pragma unroll
            for (int mt = 0; mt < 2; ++mt) {
                const int r0 = mrow + mt * 16 + gidr;
                ct[r0 * 130 + c0]           = ftanh(acc[nt][mt][0] + bs[c0]);
                ct[r0 * 130 + c0 + 1]       = ftanh(acc[nt][mt][1] + bs[c0 + 1]);
                ct[(r0 + 8) * 130 + c0]     = ftanh(acc[nt][mt][2] + bs[c0]);
                ct[(r0 + 8) * 130 + c0 + 1] = ftanh(acc[nt][mt][3] + bs[c0 + 1]);
            }
        }
    }
    __syncthreads();

    // ---- segmented reduce: nd conjs each of depth 2/4/6 -> formula ----
    for (int task = tid; task < 128 * nf; task += 256) {
        const int row = task & 127;
        const int fi  = task >> 7;
        const float* cr = &ct[row * 130 + fi * LF];
        float fs = 0.f;
        int off = 0;
        #pragma unroll
        for (int dd = 0; dd < 3; ++dd) {
            const int d = 2 + 2 * dd;
            for (int c = 0; c < nd; ++c) {
                float sA = 0.f;
                #pragma unroll
                for (int u = 0; u < 6; ++u)
                    if (u < d) sA += cr[off + u];
                fs += ftanh(sA - (float)d + 1.5f);
                off += d;
            }
        }
        g_dnnf[(size_t)(rowBase + row) * NFORM + f0g + fi] =
            ftanh(fs + 3.0f * (float)nd - 1.5f);
    }
}

// ---------------------------------------------------------------------------
// K2 fused (TF32, K=256): v = x^2.s2 + x.m2 (+c) -> loc -> softmax -> out
//   CTA M32 x N256, 8 warps (2M x 4N), 8 K32 chunks, 3-stage cp.async.
// ---------------------------------------------------------------------------
#define K2_ST(s) (1024 + (s) * 36864)       // A 4KB @ +0, B 32KB @ +4096
#define K2_SMEM  (1024 + 3 * 36864)         // 111616

__device__ __forceinline__ void k2_prefetch(int kc, uint32_t st, int tid, int xb) {
    const uint4* asrc = g_xa2 + (size_t)xb * 2048 + kc * 256;
    const uint4* bsrc = g_b2 + (size_t)kc * 2048;
    cpa16(st + tid * 16, asrc + tid);                    // 256 entries
    #pragma unroll
    for (int i = 0; i < 8; ++i) {
        int e = tid + i * 256;
        cpa16(st + 4096 + e * 16, bsrc + e);
    }
}

__global__ __launch_bounds__(256) void k2_fused(const float* __restrict__ temp,
                                                float* __restrict__ out) {
    extern __shared__ __align__(1024) char smem[];
    const uint32_t sb = smem_u32(smem);
    float* scr = reinterpret_cast<float*>(smem);         // [32 rows][4 wn] @ 0

    const int tid  = threadIdx.x;
    const int wid  = tid >> 5;
    const int lane = tid & 31;
    const int xb   = blockIdx.x;
    const int rowBase = xb * 32;

    k2_prefetch(0, sb + K2_ST(0), tid, xb);
    cpa_commit();
    k2_prefetch(1, sb + K2_ST(1), tid, xb);
    cpa_commit();

    const int wm = wid & 1, wn = wid >> 1;               // 2M x 4N
    const int mrow = wm * 16, ncol = wn * 64;
    const uint32_t aoff = (uint32_t)(wm * 2048 + lane * 16);         // + ks*512
    const uint32_t boff = (uint32_t)(4096 + wn * 8192 + lane * 16);  // + ks*2048 + p*512

    float acc[8][4];
    #pragma unroll
    for (int nt = 0; nt < 8; ++nt)
        #pragma unroll
        for (int j = 0; j < 4; ++j) acc[nt][j] = 0.f;

    #pragma unroll
    for (int kc = 0; kc < 8; ++kc) {
        if (kc < 7) cpa_wait1(); else cpa_wait0();
        __syncthreads();
        if (kc < 6) {
            k2_prefetch(kc + 2, sb + K2_ST((kc + 2) % 3), tid, xb);
            cpa_commit();
        }
        const char* st = smem + K2_ST(kc % 3);
        #pragma unroll
        for (int ks = 0; ks < 4; ++ks) {
            uint4 av = *reinterpret_cast<const uint4*>(st + aoff + ks * 512);
            #pragma unroll
            for (int p = 0; p < 4; ++p) {
                uint4 bv = *reinterpret_cast<const uint4*>(st + boff + ks * 2048 + p * 512);
                mma_tf32(acc[2*p    ], av, bv.x, bv.y);
                mma_tf32(acc[2*p + 1], av, bv.z, bv.w);
            }
        }
    }

    // ---- epilogue: z = sigmoid(T) * exp(-sqrt(v)) ----
    const float s = 1.f / (1.f + __expf(-temp[0]));
    const int gidr = lane >> 2, tig = lane & 3;

    #pragma unroll
    for (int nt = 0; nt < 8; ++nt)
        #pragma unroll
        for (int j = 0; j < 4; ++j) {
            const int col = ncol + nt * 8 + 2 * tig + (j & 1);
            float v = acc[nt][j] + __ldg(&g_c[col]);
            acc[nt][j] = s * __expf(-__fsqrt_rn(fmaxf(v, 0.f)));
        }

    // ---- row max (shfl over tig; smem across 4 N-warps) ----
    float rmax[2], rsum[2];
    #pragma unroll
    for (int hf = 0; hf < 2; ++hf) {
        float m = -1e30f;
        #pragma unroll
        for (int nt = 0; nt < 8; ++nt) {
            m = fmaxf(m, acc[nt][2*hf]);
            m = fmaxf(m, acc[nt][2*hf + 1]);
        }
        m = fmaxf(m, __shfl_xor_sync(0xFFFFFFFFu, m, 1));
        m = fmaxf(m, __shfl_xor_sync(0xFFFFFFFFu, m, 2));
        if (tig == 0) scr[(mrow + gidr + hf * 8) * 4 + wn] = m;
    }
    __syncthreads();
    #pragma unroll
    for (int hf = 0; hf < 2; ++hf) {
        const float* p = &scr[(mrow + gidr + hf * 8) * 4];
        rmax[hf] = fmaxf(fmaxf(p[0], p[1]), fmaxf(p[2], p[3]));
    }
    __syncthreads();

    #pragma unroll
    for (int hf = 0; hf < 2; ++hf) {
        float sm = 0.f;
        #pragma unroll
        for (int nt = 0; nt < 8; ++nt) {
            acc[nt][2*hf]     = __expf(acc[nt][2*hf]     - rmax[hf]);
            acc[nt][2*hf + 1] = __expf(acc[nt][2*hf + 1] - rmax[hf]);
            sm += acc[nt][2*hf] + acc[nt][2*hf + 1];
        }
        sm += __shfl_xor_sync(0xFFFFFFFFu, sm, 1);
        sm += __shfl_xor_sync(0xFFFFFFFFu, sm, 2);
        if (tig == 0) scr[(mrow + gidr + hf * 8) * 4 + wn] = sm;
    }
    __syncthreads();
    #pragma unroll
    for (int hf = 0; hf < 2; ++hf) {
        const float* p = &scr[(mrow + gidr + hf * 8) * 4];
        rsum[hf] = 1.f / (p[0] + p[1] + p[2] + p[3]);
    }

    #pragma unroll
    for (int hf = 0; hf < 2; ++hf) {
        const size_t grow = (size_t)(rowBase + mrow + gidr + hf * 8);
        const float inv = rsum[hf];
        #pragma unroll
        for (int nt = 0; nt < 8; ++nt) {
            const int col = ncol + nt * 8 + 2 * tig;
            const size_t idx = grow * NFORM + col;
            out[idx]     = g_dnnf[idx]     * acc[nt][2*hf]     * inv;
            out[idx + 1] = g_dnnf[idx + 1] * acc[nt][2*hf + 1] * inv;
        }
    }
}

// ---------------------------------------------------------------------------
extern "C" void kernel_launch(void* const* d_in, const int* in_sizes, int n_in,
                              void* d_out, int out_size) {
    const float* x     = (const float*)d_in[0];
    const float* w     = (const float*)d_in[1];
    const float* bias  = (const float*)d_in[2];
    const float* lm    = (const float*)d_in[3];
    const float* mu    = (const float*)d_in[4];
    const float* sigma = (const float*)d_in[5];
    const float* temp  = (const float*)d_in[6];
    float* out = (float*)d_out;

    cudaFuncSetAttribute(k0_prep_xa, cudaFuncAttributeMaxDynamicSharedMemorySize, PREP_SMEM);
    cudaFuncSetAttribute(k0_prep_wb, cudaFuncAttributeMaxDynamicSharedMemorySize, PREP_SMEM);
    cudaFuncSetAttribute(k1_tensor,  cudaFuncAttributeMaxDynamicSharedMemorySize, K1_SMEM);
    cudaFuncSetAttribute(k2_fused,   cudaFuncAttributeMaxDynamicSharedMemorySize, K2_SMEM);

    k0_prep_xa<<<32, 256, PREP_SMEM>>>(x);
    k0_prep_wb<<<99, 256, PREP_SMEM>>>(w, lm);
    k0_prep_b2c<<<9, 256>>>(mu, sigma);
    k1_tensor<<<dim3(32, 99), 256, K1_SMEM>>>(bias);
    k2_fused<<<BATCH / 32, 256, K2_SMEM>>>(temp, out);
}

// round 12
// speedup vs baseline: 1.5223x; 1.1345x over previous
#include <cuda_runtime.h>
#include <cuda_bf16.h>
#include <math.h>
#include <stdint.h>

#define BATCH      4096
#define DIM        128
#define NFORM      256
#define NLIT       10752

// ---------------------------------------------------------------------------
// Helpers (portable PTX only: mma.sync / cp.async / cvt.rna.tf32)
// ---------------------------------------------------------------------------
__device__ __forceinline__ float ftanh(float v) {
    float r; asm("tanh.approx.f32 %0, %1;" : "=f"(r) : "f"(v)); return r;
}
__device__ __forceinline__ uint32_t smem_u32(const void* p) {
    uint32_t a;
    asm("{ .reg .u64 t; cvta.to.shared.u64 t, %1; cvt.u32.u64 %0, t; }" : "=r"(a) : "l"(p));
    return a;
}
__device__ __forceinline__ uint32_t rna_tf32(float v) {
    uint32_t r; asm("cvt.rna.tf32.f32 %0, %1;" : "=r"(r) : "f"(v)); return r;
}
__device__ __forceinline__ void mma_tf32(float* c, uint4 a, uint32_t b0, uint32_t b1) {
    asm volatile("mma.sync.aligned.m16n8k8.row.col.f32.tf32.tf32.f32 "
                 "{%0,%1,%2,%3}, {%4,%5,%6,%7}, {%8,%9}, {%0,%1,%2,%3};"
                 : "+f"(c[0]), "+f"(c[1]), "+f"(c[2]), "+f"(c[3])
                 : "r"(a.x), "r"(a.y), "r"(a.z), "r"(a.w), "r"(b0), "r"(b1));
}
__device__ __forceinline__ void cpa16(uint32_t dst, const void* src) {
    asm volatile("cp.async.ca.shared.global [%0], [%1], 16;" :: "r"(dst), "l"(src));
}
__device__ __forceinline__ void cpa_commit() { asm volatile("cp.async.commit_group;"); }
__device__ __forceinline__ void cpa_wait1()  { asm volatile("cp.async.wait_group 1;"); }
__device__ __forceinline__ void cpa_wait0()  { asm volatile("cp.async.wait_group 0;"); }

// ---------------------------------------------------------------------------
// Scratch (device globals)
// ---------------------------------------------------------------------------
__device__ float g_dnnf[BATCH * NFORM];
__device__ float g_loc [BATCH * NFORM];
__device__ float g_c   [NFORM];
__device__ uint4 g_xa [32 * 4096];      // k1 A: tf32 fragments, per 128-row block
__device__ uint4 g_wb [99 * 4096];      // k1 B: tf32 fragments, per yy-tile
__device__ uint4 g_xa2[128 * 2048];     // k2 A: [x^2 || x], per 32-row block
__device__ uint4 g_b2 [8 * 2048];       // k2 B: [sigma^2 ; -2 mu sigma^2]

// ---------------------------------------------------------------------------
// yy-tile decode (k1)
// ---------------------------------------------------------------------------
__device__ __forceinline__ void decode_tile(int yy, int& LF, int& nd, int& nf,
                                            int& f0g, int& lb0) {
    if (yy < 13)      { LF = 24; nd = 2; nf = (yy == 12) ? 4 : 5; f0g = 5 * yy;          lb0 = 120 * yy; }
    else if (yy < 35) { int t = yy - 13; LF = 36; nd = 3; nf = (t == 21) ? 1 : 3; f0g = 64  + 3 * t; lb0 = 1536 + 108 * t; }
    else if (yy < 67) { int t = yy - 35; LF = 48; nd = 4; nf = 2; f0g = 128 + 2 * t; lb0 = 3840 + 96 * t; }
    else              { int t = yy - 67; LF = 60; nd = 5; nf = 2; f0g = 192 + 2 * t; lb0 = 6912 + 120 * t; }
}

// ---------------------------------------------------------------------------
// K0a: x -> k1 A blob (g_xa) + k2 A blob (g_xa2).  grid=128, one 32-row block
//   per CTA (rb = xb>>2, sub = xb&3; writes k1 entries with wm==sub).
// ---------------------------------------------------------------------------
#define PREP2_SMEM (32 * 132 * 4)
__global__ __launch_bounds__(256) void k0_prep_xa(const float* __restrict__ x) {
    extern __shared__ __align__(16) float xs[];          // [32][132]
    const int xb = blockIdx.x, tid = threadIdx.x;
    const int rb = xb >> 2, sub = xb & 3;
    for (int e = tid; e < 32 * 32; e += 256) {
        int r = e >> 5, c4 = e & 31;
        float4 v = reinterpret_cast<const float4*>(x + (size_t)(xb * 32 + r) * DIM)[c4];
        xs[r * 132 + c4 * 4 + 0] = v.x;
        xs[r * 132 + c4 * 4 + 1] = v.y;
        xs[r * 132 + c4 * 4 + 2] = v.z;
        xs[r * 132 + c4 * 4 + 3] = v.w;
    }
    __syncthreads();
    // k1 blob: 1024 entries (wm == sub)
    #pragma unroll
    for (int i = 0; i < 4; ++i) {
        int o = i * 256 + tid;
        int lane = o & 31, ks = (o >> 5) & 3, mt = (o >> 7) & 1, kc = (o >> 8) & 3;
        int r = mt * 16 + (lane >> 2);
        int c = kc * 32 + ks * 8 + (lane & 3);
        int go = kc * 1024 + sub * 256 + mt * 128 + ks * 32 + lane;
        g_xa[(size_t)rb * 4096 + go] =
            make_uint4(rna_tf32(xs[r * 132 + c]),     rna_tf32(xs[(r + 8) * 132 + c]),
                       rna_tf32(xs[r * 132 + c + 4]), rna_tf32(xs[(r + 8) * 132 + c + 4]));
    }
    // k2 blob: 2048 entries for this 32-row block
    #pragma unroll
    for (int i = 0; i < 8; ++i) {
        int o = i * 256 + tid;
        int lane = o & 31, ks = (o >> 5) & 3, wm = (o >> 7) & 1, kc = (o >> 8) & 7;
        int r = wm * 16 + (lane >> 2);
        int c = kc * 32 + ks * 8 + (lane & 3);
        float v0, v1, v2, v3;
        if (c < 128) {
            float a = xs[r * 132 + c],      b = xs[(r + 8) * 132 + c];
            float d = xs[r * 132 + c + 4],  e = xs[(r + 8) * 132 + c + 4];
            v0 = a * a; v1 = b * b; v2 = d * d; v3 = e * e;
        } else {
            int cc = c - 128;
            v0 = xs[r * 132 + cc];     v1 = xs[(r + 8) * 132 + cc];
            v2 = xs[r * 132 + cc + 4]; v3 = xs[(r + 8) * 132 + cc + 4];
        }
        g_xa2[(size_t)xb * 2048 + o] =
            make_uint4(rna_tf32(v0), rna_tf32(v1), rna_tf32(v2), rna_tf32(v3));
    }
}

// ---------------------------------------------------------------------------
// K0b: masked W -> k1 B blob (g_wb), per yy-tile, zero-padded
// ---------------------------------------------------------------------------
#define PREP_SMEM (128 * 132 * 4)
__global__ __launch_bounds__(256) void k0_prep_wb(const float* __restrict__ w,
                                                  const float* __restrict__ lm) {
    extern __shared__ __align__(16) float ws[];          // [128 k][132 n]
    const int yy = blockIdx.x, tid = threadIdx.x;
    int LF, nd, nf, f0g, lb0;
    decode_tile(yy, LF, nd, nf, f0g, lb0);
    const int LIVE = nf * LF;
    for (int e = tid; e < 128 * 128; e += 256) {
        int k = e >> 7, j = e & 127;
        float val = 0.f;
        if (j < LIVE) {
            int f = f0g + j / LF;
            float mk = (fabsf(lm[k * NFORM + f]) > 1.0f) ? 1.0f : 0.0f;
            val = w[(size_t)k * NLIT + lb0 + j] * mk;
        }
        ws[k * 132 + j] = val;
    }
    __syncthreads();
    #pragma unroll
    for (int i = 0; i < 16; ++i) {
        int o = i * 256 + tid;
        int lane = o & 31, p = (o >> 5) & 3, ks = (o >> 7) & 3;
        int wn = (o >> 9) & 1, kc = (o >> 10) & 3;
        int n = wn * 64 + p * 16 + (lane >> 2);
        int k = kc * 32 + ks * 8 + (lane & 3);
        g_wb[(size_t)yy * 4096 + o] =
            make_uint4(rna_tf32(ws[k * 132 + n]),     rna_tf32(ws[(k + 4) * 132 + n]),
                       rna_tf32(ws[k * 132 + n + 8]), rna_tf32(ws[(k + 4) * 132 + n + 8]));
    }
}

// ---------------------------------------------------------------------------
// K0c: k2 B blob (g_b2) + c[f].  grid = 9: blocks 0..7 -> kc, block 8 -> c[f]
// ---------------------------------------------------------------------------
__device__ __forceinline__ float b2val(const float* mu, const float* sg, int k, int n) {
    if (k < 128) { float s = sg[n * DIM + k]; return s * s; }
    int kk = k - 128;
    float s = sg[n * DIM + kk];
    return -2.f * mu[n * DIM + kk] * s * s;
}
__global__ __launch_bounds__(256) void k0_prep_b2c(const float* __restrict__ mu,
                                                   const float* __restrict__ sigma) {
    const int b = blockIdx.x, tid = threadIdx.x;
    if (b < 8) {
        #pragma unroll
        for (int i = 0; i < 8; ++i) {
            int o = i * 256 + tid;
            int lane = o & 31, p = (o >> 5) & 3, ks = (o >> 7) & 3, wn = (o >> 9) & 3;
            int n = wn * 64 + p * 16 + (lane >> 2);
            int k = b * 32 + ks * 8 + (lane & 3);
            g_b2[(size_t)b * 2048 + o] =
                make_uint4(rna_tf32(b2val(mu, sigma, k,     n)),
                           rna_tf32(b2val(mu, sigma, k + 4, n)),
                           rna_tf32(b2val(mu, sigma, k,     n + 8)),
                           rna_tf32(b2val(mu, sigma, k + 4, n + 8)));
        }
    } else {
        int f = tid;
        const float4* m4 = reinterpret_cast<const float4*>(mu + f * DIM);
        const float4* s4 = reinterpret_cast<const float4*>(sigma + f * DIM);
        float c = 0.f;
        #pragma unroll 8
        for (int i = 0; i < 32; ++i) {
            float4 m = m4[i], s = s4[i];
            c += m.x * m.x * s.x * s.x + m.y * m.y * s.y * s.y
               + m.z * m.z * s.z * s.z + m.w * m.w * s.w * s.w;
        }
        g_c[f] = c;
    }
}

// ---------------------------------------------------------------------------
// K1: single-pass TF32 literal GEMM (K=128) + fused tanh/segmented reduce
// ---------------------------------------------------------------------------
#define K1_ST(s) (1024 + (s) * 32768)
#define K1_SMEM  (1024 + 3 * 32768)

__device__ __forceinline__ void k1_prefetch(int kc, uint32_t st, int tid, int rb, int yy) {
    const uint4* asrc = g_xa + (size_t)rb * 4096 + kc * 1024;
    const uint4* bsrc = g_wb + (size_t)yy * 4096 + kc * 1024;
    #pragma unroll
    for (int i = 0; i < 4; ++i) {
        int e = tid + i * 256;
        cpa16(st + e * 16,         asrc + e);
        cpa16(st + 16384 + e * 16, bsrc + e);
    }
}

__global__ __launch_bounds__(256, 2) void k1_tensor(const float* __restrict__ bias) {
    extern __shared__ __align__(1024) char smem[];
    const uint32_t sb = smem_u32(smem);
    float* bs = reinterpret_cast<float*>(smem);

    const int tid  = threadIdx.x;
    const int wid  = tid >> 5;
    const int lane = tid & 31;
    const int rb   = blockIdx.x;
    const int yy   = blockIdx.y;
    const int rowBase = rb * 128;

    int LF, nd, nf, f0g, lb0;
    decode_tile(yy, LF, nd, nf, f0g, lb0);
    const int LIVE = nf * LF;

    if (tid < 128) bs[tid] = (tid < LIVE) ? bias[lb0 + tid] : 0.f;

    k1_prefetch(0, sb + K1_ST(0), tid, rb, yy);
    cpa_commit();
    k1_prefetch(1, sb + K1_ST(1), tid, rb, yy);
    cpa_commit();

    const int wm = wid & 3, wn = wid >> 2;
    const int mrow = wm * 32, ncol = wn * 64;
    const uint32_t aoff = (uint32_t)(wm * 4096 + lane * 16);
    const uint32_t boff = (uint32_t)(16384 + wn * 8192 + lane * 16);

    float acc[8][2][4];
    #pragma unroll
    for (int nt = 0; nt < 8; ++nt)
        #pragma unroll
        for (int mt = 0; mt < 2; ++mt)
            #pragma unroll
            for (int j = 0; j < 4; ++j) acc[nt][mt][j] = 0.f;

    #pragma unroll
    for (int kc = 0; kc < 4; ++kc) {
        if (kc < 3) cpa_wait1(); else cpa_wait0();
        __syncthreads();
        if (kc < 2) {
            k1_prefetch(kc + 2, sb + K1_ST((kc + 2) % 3), tid, rb, yy);
            cpa_commit();
        }
        const char* st = smem + K1_ST(kc % 3);
        #pragma unroll
        for (int ks = 0; ks < 4; ++ks) {
            uint4 av[2];
            av[0] = *reinterpret_cast<const uint4*>(st + aoff + ks * 512);
            av[1] = *reinterpret_cast<const uint4*>(st + aoff + 2048 + ks * 512);
            #pragma unroll
            for (int p = 0; p < 4; ++p) {
                uint4 bv = *reinterpret_cast<const uint4*>(st + boff + ks * 2048 + p * 512);
                #pragma unroll
                for (int mt = 0; mt < 2; ++mt) {
                    mma_tf32(acc[2*p    ][mt], av[mt], bv.x, bv.y);
                    mma_tf32(acc[2*p + 1][mt], av[mt], bv.z, bv.w);
                }
            }
        }
    }
    __syncthreads();

    float* ct = reinterpret_cast<float*>(smem + K1_ST(0));
    {
        const int gidr = lane >> 2, tig = lane & 3;
        #pragma unroll
        for (int nt = 0; nt < 8; ++nt) {
            const int c0 = ncol + nt * 8 + 2 * tig;
            #pragma unroll
            for (int mt = 0; mt < 2; ++mt) {
                const int r0 = mrow + mt * 16 + gidr;
                ct[r0 * 130 + c0]           = ftanh(acc[nt][mt][0] + bs[c0]);
                ct[r0 * 130 + c0 + 1]       = ftanh(acc[nt][mt][1] + bs[c0 + 1]);
                ct[(r0 + 8) * 130 + c0]     = ftanh(acc[nt][mt][2] + bs[c0]);
                ct[(r0 + 8) * 130 + c0 + 1] = ftanh(acc[nt][mt][3] + bs[c0 + 1]);
            }
        }
    }
    __syncthreads();

    for (int task = tid; task < 128 * nf; task += 256) {
        const int row = task & 127;
        const int fi  = task >> 7;
        const float* cr = &ct[row * 130 + fi * LF];
        float fs = 0.f;
        int off = 0;
        #pragma unroll
        for (int dd = 0; dd < 3; ++dd) {
            const int d = 2 + 2 * dd;
            for (int c = 0; c < nd; ++c) {
                float sA = 0.f;
                #pragma unroll
                for (int u = 0; u < 6; ++u)
                    if (u < d) sA += cr[off + u];
                fs += ftanh(sA - (float)d + 1.5f);
                off += d;
            }
        }
        g_dnnf[(size_t)(rowBase + row) * NFORM + f0g + fi] =
            ftanh(fs + 3.0f * (float)nd - 1.5f);
    }
}

// ---------------------------------------------------------------------------
// K2 (TF32, K=256): v -> loc -> row softmax -> g_loc   (no dnnf dependency)
// ---------------------------------------------------------------------------
#define K2_ST(s) (1024 + (s) * 36864)
#define K2_SMEM  (1024 + 3 * 36864)

__device__ __forceinline__ void k2_prefetch(int kc, uint32_t st, int tid, int xb) {
    const uint4* asrc = g_xa2 + (size_t)xb * 2048 + kc * 256;
    const uint4* bsrc = g_b2 + (size_t)kc * 2048;
    cpa16(st + tid * 16, asrc + tid);
    #pragma unroll
    for (int i = 0; i < 8; ++i) {
        int e = tid + i * 256;
        cpa16(st + 4096 + e * 16, bsrc + e);
    }
}

__global__ __launch_bounds__(256) void k2_loc(const float* __restrict__ temp) {
    extern __shared__ __align__(1024) char smem[];
    const uint32_t sb = smem_u32(smem);
    float* scr = reinterpret_cast<float*>(smem);

    const int tid  = threadIdx.x;
    const int wid  = tid >> 5;
    const int lane = tid & 31;
    const int xb   = blockIdx.x;
    const int rowBase = xb * 32;

    k2_prefetch(0, sb + K2_ST(0), tid, xb);
    cpa_commit();
    k2_prefetch(1, sb + K2_ST(1), tid, xb);
    cpa_commit();

    const int wm = wid & 1, wn = wid >> 1;
    const int mrow = wm * 16, ncol = wn * 64;
    const uint32_t aoff = (uint32_t)(wm * 2048 + lane * 16);
    const uint32_t boff = (uint32_t)(4096 + wn * 8192 + lane * 16);

    float acc[8][4];
    #pragma unroll
    for (int nt = 0; nt < 8; ++nt)
        #pragma unroll
        for (int j = 0; j < 4; ++j) acc[nt][j] = 0.f;

    #pragma unroll
    for (int kc = 0; kc < 8; ++kc) {
        if (kc < 7) cpa_wait1(); else cpa_wait0();
        __syncthreads();
        if (kc < 6) {
            k2_prefetch(kc + 2, sb + K2_ST((kc + 2) % 3), tid, xb);
            cpa_commit();
        }
        const char* st = smem + K2_ST(kc % 3);
        #pragma unroll
        for (int ks = 0; ks < 4; ++ks) {
            uint4 av = *reinterpret_cast<const uint4*>(st + aoff + ks * 512);
            #pragma unroll
            for (int p = 0; p < 4; ++p) {
                uint4 bv = *reinterpret_cast<const uint4*>(st + boff + ks * 2048 + p * 512);
                mma_tf32(acc[2*p    ], av, bv.x, bv.y);
                mma_tf32(acc[2*p + 1], av, bv.z, bv.w);
            }
        }
    }

    const float s = 1.f / (1.f + __expf(-temp[0]));
    const int gidr = lane >> 2, tig = lane & 3;

    #pragma unroll
    for (int nt = 0; nt < 8; ++nt)
        #pragma unroll
        for (int j = 0; j < 4; ++j) {
            const int col = ncol + nt * 8 + 2 * tig + (j & 1);
            float v = acc[nt][j] + __ldg(&g_c[col]);
            acc[nt][j] = s * __expf(-__fsqrt_rn(fmaxf(v, 0.f)));
        }

    float rmax[2], rsum[2];
    #pragma unroll
    for (int hf = 0; hf < 2; ++hf) {
        float m = -1e30f;
        #pragma unroll
        for (int nt = 0; nt < 8; ++nt) {
            m = fmaxf(m, acc[nt][2*hf]);
            m = fmaxf(m, acc[nt][2*hf + 1]);
        }
        m = fmaxf(m, __shfl_xor_sync(0xFFFFFFFFu, m, 1));
        m = fmaxf(m, __shfl_xor_sync(0xFFFFFFFFu, m, 2));
        if (tig == 0) scr[(mrow + gidr + hf * 8) * 4 + wn] = m;
    }
    __syncthreads();
    #pragma unroll
    for (int hf = 0; hf < 2; ++hf) {
        const float* p = &scr[(mrow + gidr + hf * 8) * 4];
        rmax[hf] = fmaxf(fmaxf(p[0], p[1]), fmaxf(p[2], p[3]));
    }
    __syncthreads();

    #pragma unroll
    for (int hf = 0; hf < 2; ++hf) {
        float sm = 0.f;
        #pragma unroll
        for (int nt = 0; nt < 8; ++nt) {
            acc[nt][2*hf]     = __expf(acc[nt][2*hf]     - rmax[hf]);
            acc[nt][2*hf + 1] = __expf(acc[nt][2*hf + 1] - rmax[hf]);
            sm += acc[nt][2*hf] + acc[nt][2*hf + 1];
        }
        sm += __shfl_xor_sync(0xFFFFFFFFu, sm, 1);
        sm += __shfl_xor_sync(0xFFFFFFFFu, sm, 2);
        if (tig == 0) scr[(mrow + gidr + hf * 8) * 4 + wn] = sm;
    }
    __syncthreads();
    #pragma unroll
    for (int hf = 0; hf < 2; ++hf) {
        const float* p = &scr[(mrow + gidr + hf * 8) * 4];
        rsum[hf] = 1.f / (p[0] + p[1] + p[2] + p[3]);
    }

    #pragma unroll
    for (int hf = 0; hf < 2; ++hf) {
        const size_t grow = (size_t)(rowBase + mrow + gidr + hf * 8);
        const float inv = rsum[hf];
        #pragma unroll
        for (int nt = 0; nt < 8; ++nt) {
            const int col = ncol + nt * 8 + 2 * tig;
            const size_t idx = grow * NFORM + col;
            g_loc[idx]     = acc[nt][2*hf]     * inv;
            g_loc[idx + 1] = acc[nt][2*hf + 1] * inv;
        }
    }
}

// ---------------------------------------------------------------------------
// K3: out = dnnf * loc   (pure streaming)
// ---------------------------------------------------------------------------
__global__ __launch_bounds__(256) void k3_mul(float* __restrict__ out) {
    const size_t i = (size_t)blockIdx.x * 256 + threadIdx.x;   // float4 index
    float4 a = reinterpret_cast<const float4*>(g_dnnf)[i];
    float4 b = reinterpret_cast<const float4*>(g_loc)[i];
    reinterpret_cast<float4*>(out)[i] =
        make_float4(a.x * b.x, a.y * b.y, a.z * b.z, a.w * b.w);
}

// ---------------------------------------------------------------------------
extern "C" void kernel_launch(void* const* d_in, const int* in_sizes, int n_in,
                              void* d_out, int out_size) {
    const float* x     = (const float*)d_in[0];
    const float* w     = (const float*)d_in[1];
    const float* bias  = (const float*)d_in[2];
    const float* lm    = (const float*)d_in[3];
    const float* mu    = (const float*)d_in[4];
    const float* sigma = (const float*)d_in[5];
    const float* temp  = (const float*)d_in[6];
    float* out = (float*)d_out;

    cudaFuncSetAttribute(k0_prep_xa, cudaFuncAttributeMaxDynamicSharedMemorySize, PREP2_SMEM);
    cudaFuncSetAttribute(k0_prep_wb, cudaFuncAttributeMaxDynamicSharedMemorySize, PREP_SMEM);
    cudaFuncSetAttribute(k1_tensor,  cudaFuncAttributeMaxDynamicSharedMemorySize, K1_SMEM);
    cudaFuncSetAttribute(k2_loc,     cudaFuncAttributeMaxDynamicSharedMemorySize, K2_SMEM);

    // Second stream + events (fork/join inside graph capture).
    cudaStream_t s2;
    cudaStreamCreateWithFlags(&s2, cudaStreamNonBlocking);
    cudaEvent_t evXA, evK2;
    cudaEventCreateWithFlags(&evXA, cudaEventDisableTiming);
    cudaEventCreateWithFlags(&evK2, cudaEventDisableTiming);

    // main: prep_xa -> prep_wb -> k1 -> (wait k2) -> k3
    k0_prep_xa<<<128, 256, PREP2_SMEM>>>(x);
    cudaEventRecord(evXA, 0);                 // xa done (also forks s2 into capture)
    cudaStreamWaitEvent(s2, evXA, 0);
    k0_prep_wb<<<99, 256, PREP_SMEM>>>(w, lm);
    // s2: b2c -> k2_loc (runs concurrently with wb + k1)
    k0_prep_b2c<<<9, 256, 0, s2>>>(mu, sigma);
    k2_loc<<<BATCH / 32, 256, K2_SMEM, s2>>>(temp);
    cudaEventRecord(evK2, s2);
    // main: big GEMM, then join and multiply
    k1_tensor<<<dim3(32, 99), 256, K1_SMEM>>>(bias);
    cudaStreamWaitEvent(0, evK2, 0);
    k3_mul<<<BATCH * NFORM / 1024, 256>>>(out);
}